// round 2
// baseline (speedup 1.0000x reference)
#include <cuda_runtime.h>
#include <math.h>

#define NB   64      // batch
#define TE   512     // encoder length
#define KSZ  128     // key size
#define VSZ  128     // value size
#define HD   512     // hidden dim
#define TD   99      // decode steps (T_dec - 1)
#define VOC  32000
#define K1   1152    // HD + VSZ + HD
#define G1   2048    // 4*HD
#define K2   640     // HD + KSZ
#define G2   512     // 4*KSZ
#define MROWS 6336   // TD*NB
#define MPAD  6400

// ---------------- scratch (static device memory; no runtime alloc) ----------------
__device__ float g_W1T[K1 * G1];     // [k][g] combined (Wih1|Whh1)^T
__device__ float g_b1[G1];
__device__ float g_W2T[K2 * G2];     // [k][g] combined (Wih2|Whh2)^T
__device__ float g_b2[G2];
__device__ float g_embs[TD * NB * HD];
__device__ float g_h1[NB * HD];
__device__ float g_c1[NB * HD];
__device__ float g_h2[NB * KSZ];
__device__ float g_c2[NB * KSZ];
__device__ float g_ctx[NB * VSZ];
__device__ float g_gates1[NB * G1];
__device__ float g_gates2[NB * G2];
__device__ float g_A[MPAD * 256];    // [t*64+n][h2|ctx], zero-padded rows

__device__ __forceinline__ float sigf(float x) { return 1.f / (1.f + expf(-x)); }

__device__ __forceinline__ float tf32r(float x) {
    asm("cvt.rna.tf32.f32 %0, %0;" : "+f"(x));
    return x;
}

// ---------------- setup: weight repack, bias combine, state zero, emb gather ------
__global__ void setup_kernel(const float* __restrict__ Wih1, const float* __restrict__ Whh1,
                             const float* __restrict__ bih1, const float* __restrict__ bhh1,
                             const float* __restrict__ Wih2, const float* __restrict__ Whh2,
                             const float* __restrict__ bih2, const float* __restrict__ bhh2,
                             const float* __restrict__ embedding, const int* __restrict__ text)
{
    const long NW1 = (long)K1 * G1;          // 2359296
    const long NW2 = (long)K2 * G2;          // 327680
    const long NST = NB * HD * 2 + NB * KSZ * 2 + NB * VSZ;  // 90112
    const long NEMB = (long)TD * NB * HD;    // 3244032
    const long NPAD = (MPAD - MROWS) * 256;  // 16384
    const long total = NW1 + NW2 + G1 + G2 + NST + NEMB + NPAD;
    const long stride = (long)gridDim.x * blockDim.x;

    for (long idx = (long)blockIdx.x * blockDim.x + threadIdx.x; idx < total; idx += stride) {
        long i = idx;
        if (i < NW1) {
            int k = (int)(i / G1), g = (int)(i % G1);
            g_W1T[i] = (k < HD + VSZ) ? Wih1[(long)g * (HD + VSZ) + k]
                                      : Whh1[(long)g * HD + (k - (HD + VSZ))];
            continue;
        }
        i -= NW1;
        if (i < NW2) {
            int k = (int)(i / G2), g = (int)(i % G2);
            g_W2T[i] = (k < HD) ? Wih2[(long)g * HD + k]
                                : Whh2[(long)g * KSZ + (k - HD)];
            continue;
        }
        i -= NW2;
        if (i < G1) { g_b1[i] = bih1[i] + bhh1[i]; continue; }
        i -= G1;
        if (i < G2) { g_b2[i] = bih2[i] + bhh2[i]; continue; }
        i -= G2;
        if (i < NST) {
            if (i < NB * HD) g_h1[i] = 0.f;
            else if (i < 2 * NB * HD) g_c1[i - NB * HD] = 0.f;
            else {
                long j = i - 2 * NB * HD;
                if (j < NB * KSZ) g_h2[j] = 0.f;
                else if (j < 2 * NB * KSZ) g_c2[j - NB * KSZ] = 0.f;
                else g_ctx[j - 2 * NB * KSZ] = 0.f;
            }
            continue;
        }
        i -= NST;
        if (i < NEMB) {
            int t = (int)(i / (NB * HD));
            int r = (int)(i % (NB * HD));
            int n = r >> 9, d = r & (HD - 1);
            int tok = text[n * 100 + t];
            g_embs[i] = embedding[(size_t)tok * HD + d];
            continue;
        }
        i -= NEMB;
        g_A[(size_t)MROWS * 256 + i] = 0.f;
    }
}

// ---------------- gate GEMM: gates[n][g] = u[n] . WT[:,g] + b[g] -----------------
// block: 64 gate cols x 16 batch rows; 256 threads, each computes 4 (n) outputs
template <int L>
__global__ __launch_bounds__(256) void gates_kernel(int t)
{
    constexpr int K = (L == 1) ? K1 : K2;
    constexpr int G = (L == 1) ? G1 : G2;
    const float* __restrict__ WT   = (L == 1) ? g_W1T : g_W2T;
    const float* __restrict__ bias = (L == 1) ? g_b1 : g_b2;
    float* __restrict__ gout       = (L == 1) ? g_gates1 : g_gates2;

    extern __shared__ float us[];   // [16][K]
    const int tid = threadIdx.x;
    const int g0 = blockIdx.x * 64;
    const int n0 = blockIdx.y * 16;

    for (int nl = 0; nl < 16; nl++) {
        const int n = n0 + nl;
        float* ur = us + nl * K;
        if (L == 1) {
            const float* e = g_embs + ((size_t)t * NB + n) * HD;
            for (int k = tid; k < HD; k += 256) ur[k] = e[k];
            for (int k = tid; k < VSZ; k += 256) ur[HD + k] = g_ctx[n * VSZ + k];
            for (int k = tid; k < HD; k += 256) ur[HD + VSZ + k] = g_h1[n * HD + k];
        } else {
            for (int k = tid; k < HD; k += 256) ur[k] = g_h1[n * HD + k];
            for (int k = tid; k < KSZ; k += 256) ur[HD + k] = g_h2[n * KSZ + k];
        }
    }
    __syncthreads();

    const int col = g0 + (tid & 63);
    const int nsub = tid >> 6;     // 0..3
    const float* u0 = us + (nsub * 4 + 0) * K;
    const float* u1 = us + (nsub * 4 + 1) * K;
    const float* u2 = us + (nsub * 4 + 2) * K;
    const float* u3 = us + (nsub * 4 + 3) * K;
    const float* wp = WT + col;

    float a0 = 0.f, a1 = 0.f, a2 = 0.f, a3 = 0.f;
#pragma unroll 4
    for (int k = 0; k < K; k += 4) {
        float w0 = wp[(size_t)(k + 0) * G];
        float w1 = wp[(size_t)(k + 1) * G];
        float w2 = wp[(size_t)(k + 2) * G];
        float w3 = wp[(size_t)(k + 3) * G];
        float4 x0 = *(const float4*)(u0 + k);
        float4 x1 = *(const float4*)(u1 + k);
        float4 x2 = *(const float4*)(u2 + k);
        float4 x3 = *(const float4*)(u3 + k);
        a0 = fmaf(x0.x, w0, a0); a0 = fmaf(x0.y, w1, a0); a0 = fmaf(x0.z, w2, a0); a0 = fmaf(x0.w, w3, a0);
        a1 = fmaf(x1.x, w0, a1); a1 = fmaf(x1.y, w1, a1); a1 = fmaf(x1.z, w2, a1); a1 = fmaf(x1.w, w3, a1);
        a2 = fmaf(x2.x, w0, a2); a2 = fmaf(x2.y, w1, a2); a2 = fmaf(x2.z, w2, a2); a2 = fmaf(x2.w, w3, a2);
        a3 = fmaf(x3.x, w0, a3); a3 = fmaf(x3.y, w1, a3); a3 = fmaf(x3.z, w2, a3); a3 = fmaf(x3.w, w3, a3);
    }
    const float b = bias[col];
    const int nb = n0 + nsub * 4;
    gout[(size_t)(nb + 0) * G + col] = a0 + b;
    gout[(size_t)(nb + 1) * G + col] = a1 + b;
    gout[(size_t)(nb + 2) * G + col] = a2 + b;
    gout[(size_t)(nb + 3) * G + col] = a3 + b;
}

// ---------------- LSTM1 cell update ----------------------------------------------
__global__ __launch_bounds__(256) void cell1_kernel()
{
    const int idx = blockIdx.x * 256 + threadIdx.x;   // < 64*512
    const int n = idx >> 9, d = idx & 511;
    const float* gg = g_gates1 + (size_t)n * G1;
    float gi = gg[d], gf = gg[HD + d], gc = gg[2 * HD + d], go = gg[3 * HD + d];
    float c = sigf(gf) * g_c1[idx] + sigf(gi) * tanhf(gc);
    g_c1[idx] = c;
    g_h1[idx] = sigf(go) * tanhf(c);
}

// ---------------- fused LSTM2 cell + attention (one block per batch element) -----
__global__ __launch_bounds__(256) void attn_kernel(const float* __restrict__ enc_key,
                                                   const float* __restrict__ values,
                                                   const int* __restrict__ lens,
                                                   float* __restrict__ attn_out, int t)
{
    const int n = blockIdx.x;
    const int tid = threadIdx.x;
    const int lane = tid & 31;
    const int w = tid >> 5;

    __shared__ __align__(16) float h2s[KSZ];
    __shared__ float es[TE];
    __shared__ float red[64];

    if (tid < KSZ) {
        const int d = tid;
        const float* gg = g_gates2 + (size_t)n * G2;
        float gi = gg[d], gf = gg[KSZ + d], gc = gg[2 * KSZ + d], go = gg[3 * KSZ + d];
        float c = sigf(gf) * g_c2[n * KSZ + d] + sigf(gi) * tanhf(gc);
        float h = sigf(go) * tanhf(c);
        g_c2[n * KSZ + d] = c;
        g_h2[n * KSZ + d] = h;
        h2s[d] = h;
        g_A[((size_t)t * NB + n) * 256 + d] = h;
    }
    __syncthreads();

    // energy[s] = enc_key[n,s,:] . h2  (one warp covers 64 s values)
    const float* ek = enc_key + (size_t)n * TE * KSZ;
    float4 hq = ((const float4*)h2s)[lane];
    for (int s = w * 64; s < w * 64 + 64; s++) {
        float4 kv = ((const float4*)(ek + (size_t)s * KSZ))[lane];
        float p = kv.x * hq.x + kv.y * hq.y + kv.z * hq.z + kv.w * hq.w;
        p += __shfl_down_sync(0xffffffffu, p, 16);
        p += __shfl_down_sync(0xffffffffu, p, 8);
        p += __shfl_down_sync(0xffffffffu, p, 4);
        p += __shfl_down_sync(0xffffffffu, p, 2);
        p += __shfl_down_sync(0xffffffffu, p, 1);
        if (lane == 0) es[s] = p;
    }
    __syncthreads();

    // max over all 512 (matches ref softmax), then masked exp + renorm
    float m = fmaxf(es[tid], es[tid + 256]);
#pragma unroll
    for (int o = 16; o; o >>= 1) m = fmaxf(m, __shfl_xor_sync(0xffffffffu, m, o));
    if (lane == 0) red[w] = m;
    __syncthreads();
    if (tid == 0) {
        float mm = red[0];
        for (int i = 1; i < 8; i++) mm = fmaxf(mm, red[i]);
        red[32] = mm;
    }
    __syncthreads();
    m = red[32];
    const int len = lens[n];
    float p0 = (tid < len) ? expf(es[tid] - m) : 0.f;
    float p1 = (tid + 256 < len) ? expf(es[tid + 256] - m) : 0.f;
    float ssum = p0 + p1;
#pragma unroll
    for (int o = 16; o; o >>= 1) ssum += __shfl_xor_sync(0xffffffffu, ssum, o);
    if (lane == 0) red[w] = ssum;
    __syncthreads();
    if (tid == 0) {
        float ss = 0.f;
        for (int i = 0; i < 8; i++) ss += red[i];
        red[33] = ss;
    }
    __syncthreads();
    const float inv = 1.f / red[33];
    const float a0v = p0 * inv, a1v = p1 * inv;
    es[tid] = a0v;
    es[tid + 256] = a1v;
    float* ao = attn_out + ((size_t)n * TD + t) * TE;
    ao[tid] = a0v;
    ao[tid + 256] = a1v;
    __syncthreads();

    // context[k] = sum_s attn[s] * values[n,s,k]
    if (tid < VSZ) {
        const float* vv = values + (size_t)n * TE * VSZ + tid;
        float acc = 0.f;
#pragma unroll 8
        for (int s = 0; s < TE; s++) acc = fmaf(es[s], vv[(size_t)s * VSZ], acc);
        g_ctx[n * VSZ + tid] = acc;
        g_A[((size_t)t * NB + n) * 256 + KSZ + tid] = acc;
    }
}

// ---------------- final logits GEMM: out = A[6336,256] @ Wout^T + bout (tf32 mma) -
__global__ __launch_bounds__(256) void out_gemm(const float* __restrict__ B,
                                                const float* __restrict__ bout,
                                                float* __restrict__ out)
{
    __shared__ float As[128][36];
    __shared__ float Bs[128][36];
    const int tid = threadIdx.x;
    const int lane = tid & 31;
    const int warp = tid >> 5;
    const int wm = warp & 1;    // 2 warps along M
    const int wn = warp >> 1;   // 4 warps along N
    const int mBase = blockIdx.y * 128;
    const int nBase = blockIdx.x * 128;

    float acc[4][4][4];
#pragma unroll
    for (int i = 0; i < 4; i++)
#pragma unroll
        for (int j = 0; j < 4; j++)
#pragma unroll
            for (int q = 0; q < 4; q++) acc[i][j][q] = 0.f;

    const int lr = tid >> 3;
    const int kq = (tid & 7) * 4;

    for (int k0 = 0; k0 < 256; k0 += 32) {
#pragma unroll
        for (int p = 0; p < 4; p++) {
            int row = lr + p * 32;
            float4 va = *(const float4*)(g_A + (size_t)(mBase + row) * 256 + k0 + kq);
            float4 vb = *(const float4*)(B + (size_t)(nBase + row) * 256 + k0 + kq);
            va.x = tf32r(va.x); va.y = tf32r(va.y); va.z = tf32r(va.z); va.w = tf32r(va.w);
            vb.x = tf32r(vb.x); vb.y = tf32r(vb.y); vb.z = tf32r(vb.z); vb.w = tf32r(vb.w);
            *(float4*)&As[row][kq] = va;
            *(float4*)&Bs[row][kq] = vb;
        }
        __syncthreads();
#pragma unroll
        for (int ks = 0; ks < 4; ks++) {
            unsigned af[4][4], bf[4][2];
            const int ar = wm * 64 + (lane >> 2);
            const int ac = ks * 8 + (lane & 3);
#pragma unroll
            for (int mt = 0; mt < 4; mt++) {
                af[mt][0] = __float_as_uint(As[ar + mt * 16][ac]);
                af[mt][1] = __float_as_uint(As[ar + mt * 16 + 8][ac]);
                af[mt][2] = __float_as_uint(As[ar + mt * 16][ac + 4]);
                af[mt][3] = __float_as_uint(As[ar + mt * 16 + 8][ac + 4]);
            }
            const int br = wn * 32 + (lane >> 2);
#pragma unroll
            for (int nt = 0; nt < 4; nt++) {
                bf[nt][0] = __float_as_uint(Bs[br + nt * 8][ac]);
                bf[nt][1] = __float_as_uint(Bs[br + nt * 8][ac + 4]);
            }
#pragma unroll
            for (int mt = 0; mt < 4; mt++)
#pragma unroll
                for (int nt = 0; nt < 4; nt++)
                    asm volatile(
                        "mma.sync.aligned.m16n8k8.row.col.f32.tf32.tf32.f32 "
                        "{%0,%1,%2,%3},{%4,%5,%6,%7},{%8,%9},{%0,%1,%2,%3};\n"
                        : "+f"(acc[mt][nt][0]), "+f"(acc[mt][nt][1]),
                          "+f"(acc[mt][nt][2]), "+f"(acc[mt][nt][3])
                        : "r"(af[mt][0]), "r"(af[mt][1]), "r"(af[mt][2]), "r"(af[mt][3]),
                          "r"(bf[nt][0]), "r"(bf[nt][1]));
        }
        __syncthreads();
    }

    // epilogue: permuted rows (t*64+n -> n*99+t), float2 streaming stores
#pragma unroll
    for (int mt = 0; mt < 4; mt++) {
#pragma unroll
        for (int half = 0; half < 2; half++) {
            int gRow = mBase + wm * 64 + mt * 16 + (lane >> 2) + half * 8;
            if (gRow < MROWS) {
                int outRow = (gRow & 63) * TD + (gRow >> 6);
                float* op = out + (size_t)outRow * VOC + nBase + wn * 32 + (lane & 3) * 2;
#pragma unroll
                for (int nt = 0; nt < 4; nt++) {
                    int bc = nBase + wn * 32 + nt * 8 + (lane & 3) * 2;
                    float2 v;
                    v.x = acc[mt][nt][half * 2 + 0] + bout[bc];
                    v.y = acc[mt][nt][half * 2 + 1] + bout[bc + 1];
                    __stcs(reinterpret_cast<float2*>(op + nt * 8), v);
                }
            }
        }
    }
}

// ---------------- launch ----------------------------------------------------------
extern "C" void kernel_launch(void* const* d_in, const int* in_sizes, int n_in,
                              void* d_out, int out_size)
{
    const float* enc_key   = (const float*)d_in[0];
    const float* values    = (const float*)d_in[1];
    const int*   lens      = (const int*)d_in[2];
    const int*   text      = (const int*)d_in[3];
    const float* embedding = (const float*)d_in[4];
    const float* Wih1 = (const float*)d_in[5];
    const float* Whh1 = (const float*)d_in[6];
    const float* bih1 = (const float*)d_in[7];
    const float* bhh1 = (const float*)d_in[8];
    const float* Wih2 = (const float*)d_in[9];
    const float* Whh2 = (const float*)d_in[10];
    const float* bih2 = (const float*)d_in[11];
    const float* bhh2 = (const float*)d_in[12];
    const float* Wout = (const float*)d_in[13];
    const float* bout = (const float*)d_in[14];

    float* out = (float*)d_out;
    float* attn_out = out + (size_t)MROWS * VOC;

    cudaFuncSetAttribute((const void*)gates_kernel<1>,
                         cudaFuncAttributeMaxDynamicSharedMemorySize, 16 * K1 * 4);

    setup_kernel<<<8192, 256>>>(Wih1, Whh1, bih1, bhh1, Wih2, Whh2, bih2, bhh2,
                                embedding, text);

    for (int t = 0; t < TD; t++) {
        gates_kernel<1><<<dim3(G1 / 64, 4), 256, 16 * K1 * 4>>>(t);
        cell1_kernel<<<(NB * HD) / 256, 256>>>();
        gates_kernel<2><<<dim3(G2 / 64, 4), 256, 16 * K2 * 4>>>(t);
        attn_kernel<<<NB, 256>>>(enc_key, values, lens, attn_out, t);
    }

    out_gemm<<<dim3(VOC / 128, MPAD / 128), 256>>>(Wout, bout, out);
}

// round 4
// speedup vs baseline: 1.6281x; 1.6281x over previous
#include <cuda_runtime.h>
#include <math.h>

#define NB   64
#define TE   512
#define KSZ  128
#define VSZ  128
#define HD   512
#define TD   99
#define VOC  32000
#define MROWS 6336
#define MPAD  6400
#define NBLK  128
#define G1   2048
#define G2   512
#define KREC 640            // serial K for both gate GEMMs

// ---------------- static device scratch ----------------
__device__ float g_embs[(size_t)MPAD * HD];          // 13.1 MB
__device__ float g_pre1[(size_t)MPAD * G1];          // 52.4 MB (emb part of gates1)
__device__ float g_A[(size_t)MPAD * 256];            // [t*64+n][h2|ctx]
__device__ float g_h1[2][NB * HD];
__device__ float g_c1[NB * HD];
__device__ float g_h2[2][NB * KSZ];
__device__ float g_c2[NB * KSZ];
__device__ float g_ctx[NB * VSZ];
__device__ float g_b1[G1];
__device__ float g_b2[G2];
__device__ int g_bar_cnt = 0;
__device__ volatile int g_bar_gen = 0;

__device__ __forceinline__ float sigf(float x) { return 1.f / (1.f + expf(-x)); }

__device__ __forceinline__ float tf32r(float x) {
    asm("cvt.rna.tf32.f32 %0, %0;" : "+f"(x));
    return x;
}

// grid-wide barrier across NBLK resident blocks
__device__ __forceinline__ void gbar() {
    __syncthreads();
    if (threadIdx.x == 0) {
        int gen = g_bar_gen;
        __threadfence();
        if (atomicAdd(&g_bar_cnt, 1) == NBLK - 1) {
            g_bar_cnt = 0;
            __threadfence();
            g_bar_gen = gen + 1;
        } else {
            while (g_bar_gen == gen) __nanosleep(64);
            __threadfence();
        }
    }
    __syncthreads();
}

// ---------------- setup: states, biases, embedding gather ----------------
__global__ void setup_kernel(const float* __restrict__ bih1, const float* __restrict__ bhh1,
                             const float* __restrict__ bih2, const float* __restrict__ bhh2,
                             const float* __restrict__ embedding, const int* __restrict__ text)
{
    const long S_B1 = G1, S_B2 = G2;
    const long S_H1 = 2L * NB * HD, S_C1 = NB * HD;
    const long S_H2 = 2L * NB * KSZ, S_C2 = NB * KSZ, S_CTX = NB * VSZ;
    const long S_EMB = (long)MPAD * HD;
    const long S_APAD = (long)(MPAD - MROWS) * 256;
    const long total = S_B1 + S_B2 + S_H1 + S_C1 + S_H2 + S_C2 + S_CTX + S_EMB + S_APAD;
    const long stride = (long)gridDim.x * blockDim.x;

    for (long idx = (long)blockIdx.x * blockDim.x + threadIdx.x; idx < total; idx += stride) {
        long i = idx;
        if (i < S_B1) { g_b1[i] = bih1[i] + bhh1[i]; continue; } i -= S_B1;
        if (i < S_B2) { g_b2[i] = bih2[i] + bhh2[i]; continue; } i -= S_B2;
        if (i < S_H1) { ((float*)g_h1)[i] = 0.f; continue; } i -= S_H1;
        if (i < S_C1) { g_c1[i] = 0.f; continue; } i -= S_C1;
        if (i < S_H2) { ((float*)g_h2)[i] = 0.f; continue; } i -= S_H2;
        if (i < S_C2) { g_c2[i] = 0.f; continue; } i -= S_C2;
        if (i < S_CTX){ g_ctx[i] = 0.f; continue; } i -= S_CTX;
        if (i < S_EMB) {
            long row = i / HD; int d = (int)(i % HD);
            if (row < MROWS) {
                int t = (int)(row >> 6), n = (int)(row & 63);
                int tok = text[n * 100 + t];
                g_embs[i] = embedding[(size_t)tok * HD + d];
            } else g_embs[i] = 0.f;
            continue;
        }
        i -= S_EMB;
        g_A[(size_t)MROWS * 256 + i] = 0.f;
    }
}

// ---------------- tf32 GEMM: g_pre1[6400,2048] = g_embs[6400,512] @ Wih1[:, :512]^T --
__global__ __launch_bounds__(256) void pre_gemm(const float* __restrict__ B)
{
    __shared__ float As[128][36];
    __shared__ float Bs[128][36];
    const int tid = threadIdx.x;
    const int lane = tid & 31;
    const int warp = tid >> 5;
    const int wm = warp & 1;
    const int wn = warp >> 1;
    const int mBase = blockIdx.y * 128;
    const int nBase = blockIdx.x * 128;

    float acc[4][4][4];
#pragma unroll
    for (int i = 0; i < 4; i++)
#pragma unroll
        for (int j = 0; j < 4; j++)
#pragma unroll
            for (int q = 0; q < 4; q++) acc[i][j][q] = 0.f;

    const int lr = tid >> 3;
    const int kq = (tid & 7) * 4;

    for (int k0 = 0; k0 < 512; k0 += 32) {
#pragma unroll
        for (int p = 0; p < 4; p++) {
            int row = lr + p * 32;
            float4 va = *(const float4*)(g_embs + (size_t)(mBase + row) * 512 + k0 + kq);
            float4 vb = *(const float4*)(B + (size_t)(nBase + row) * 640 + k0 + kq);
            va.x = tf32r(va.x); va.y = tf32r(va.y); va.z = tf32r(va.z); va.w = tf32r(va.w);
            vb.x = tf32r(vb.x); vb.y = tf32r(vb.y); vb.z = tf32r(vb.z); vb.w = tf32r(vb.w);
            *(float4*)&As[row][kq] = va;
            *(float4*)&Bs[row][kq] = vb;
        }
        __syncthreads();
#pragma unroll
        for (int ks = 0; ks < 4; ks++) {
            unsigned af[4][4], bf[4][2];
            const int ar = wm * 64 + (lane >> 2);
            const int ac = ks * 8 + (lane & 3);
#pragma unroll
            for (int mt = 0; mt < 4; mt++) {
                af[mt][0] = __float_as_uint(As[ar + mt * 16][ac]);
                af[mt][1] = __float_as_uint(As[ar + mt * 16 + 8][ac]);
                af[mt][2] = __float_as_uint(As[ar + mt * 16][ac + 4]);
                af[mt][3] = __float_as_uint(As[ar + mt * 16 + 8][ac + 4]);
            }
            const int br = wn * 32 + (lane >> 2);
#pragma unroll
            for (int nt = 0; nt < 4; nt++) {
                bf[nt][0] = __float_as_uint(Bs[br + nt * 8][ac]);
                bf[nt][1] = __float_as_uint(Bs[br + nt * 8][ac + 4]);
            }
#pragma unroll
            for (int mt = 0; mt < 4; mt++)
#pragma unroll
                for (int nt = 0; nt < 4; nt++)
                    asm volatile(
                        "mma.sync.aligned.m16n8k8.row.col.f32.tf32.tf32.f32 "
                        "{%0,%1,%2,%3},{%4,%5,%6,%7},{%8,%9},{%0,%1,%2,%3};\n"
                        : "+f"(acc[mt][nt][0]), "+f"(acc[mt][nt][1]),
                          "+f"(acc[mt][nt][2]), "+f"(acc[mt][nt][3])
                        : "r"(af[mt][0]), "r"(af[mt][1]), "r"(af[mt][2]), "r"(af[mt][3]),
                          "r"(bf[nt][0]), "r"(bf[nt][1]));
        }
        __syncthreads();
    }

#pragma unroll
    for (int mt = 0; mt < 4; mt++)
#pragma unroll
        for (int half = 0; half < 2; half++) {
            int gRow = mBase + wm * 64 + mt * 16 + (lane >> 2) + half * 8;
            float* op = g_pre1 + (size_t)gRow * G1 + nBase + wn * 32 + (lane & 3) * 2;
#pragma unroll
            for (int nt = 0; nt < 4; nt++) {
                float2 v;
                v.x = acc[mt][nt][half * 2 + 0];
                v.y = acc[mt][nt][half * 2 + 1];
                *reinterpret_cast<float2*>(op + nt * 8) = v;
            }
        }
}

// ---------------- persistent decode kernel ----------------
// smem layout (floats)
#define OFF_WS1  0
#define WS_STR   644
#define OFF_WS2  (16 * WS_STR)                 // 10304
#define OFF_US   (2 * 16 * WS_STR)             // 20608
#define OFF_GS   (OFF_US + 8192)               // 28800
#define OFF_GS2  (OFF_GS + 64 * 17)            // 29888
#define OFF_ES   (OFF_GS2 + 16 * 17)           // 30160
#define OFF_H2S  (OFF_ES + 512)                // 30672
#define OFF_RED  (OFF_H2S + 128)               // 30800
#define OFF_CTXS (OFF_RED + 64)                // 30864
#define SMEM_FLOATS (OFF_CTXS + 256)           // 31120
#define SMEM_BYTES  (SMEM_FLOATS * 4)

__global__ __launch_bounds__(256, 1) void decode_kernel(
    const float* __restrict__ enc_key, const float* __restrict__ values,
    const int* __restrict__ lens,
    const float* __restrict__ Wih1, const float* __restrict__ Whh1,
    const float* __restrict__ Wih2, const float* __restrict__ Whh2,
    float* __restrict__ attn_out)
{
    extern __shared__ float sm[];
    const int bi = blockIdx.x;
    const int tid = threadIdx.x;
    const int lane = tid & 31;
    const int wrp = tid >> 5;

    // ---- phase-A role constants: block owns d in [d0, d0+4) of h1 ----
    const int d0 = bi * 4;
    const int cidx = tid & 15;          // col within 16-col slice: gate*4+dl
    const int ngrp = tid >> 4;          // 16 batch groups of 4
    const int gateA = cidx >> 2, dlA = cidx & 3;
    const int gcol = gateA * HD + d0 + dlA;

    // ---- phase-B role constants: block owns 4 d2 x 16 batches ----
    const int d2base = (bi >> 2) * 4;
    const int nq = bi & 3;
    const int gateB = cidx >> 2, dlB = cidx & 3;
    const int g2col = gateB * KSZ + d2base + dlB;
    const int nB0 = nq * 16;

    // load weight slices into smem (once)
    for (int i = tid; i < 16 * KREC; i += 256) {
        int c = i / KREC, k = i % KREC;
        int g = (c >> 2) * HD + d0 + (c & 3);
        float w = (k < VSZ) ? Wih1[(size_t)g * (HD + VSZ) + HD + k]
                            : Whh1[(size_t)g * HD + (k - VSZ)];
        sm[OFF_WS1 + c * WS_STR + k] = w;
    }
    for (int i = tid; i < 16 * KREC; i += 256) {
        int c = i / KREC, k = i % KREC;
        int g = (c >> 2) * KSZ + d2base + (c & 3);
        float w = (k < HD) ? Wih2[(size_t)g * HD + k]
                           : Whh2[(size_t)g * KSZ + (k - HD)];
        sm[OFF_WS2 + c * WS_STR + k] = w;
    }
    __syncthreads();

    const float bias1 = g_b1[gcol];
    const float bias2 = g_b2[g2col];
    const int len = (bi < NB) ? lens[bi] : 0;
    const int kk_fix = tid & 63;
    float* US = sm + OFF_US;

    for (int t = 0; t < TD; t++) {
        // =============== PHASE A: gates1 + cell1 ===============
        {
            const float* h1r = g_h1[t & 1];
            float* h1w = g_h1[(t + 1) & 1];
            float a0 = 0.f, a1 = 0.f, a2 = 0.f, a3 = 0.f;
            float pf[16];

            // prefetch tile 0
            {
                int k = kk_fix;
#pragma unroll
                for (int j = 0; j < 16; j++) {
                    int e = tid + j * 256, n = e >> 6;
                    pf[j] = (k < VSZ) ? g_ctx[n * VSZ + k] : h1r[n * HD + (k - VSZ)];
                }
#pragma unroll
                for (int j = 0; j < 16; j++) US[tid + j * 256] = pf[j];
            }
            __syncthreads();
            int buf = 0;
            for (int tile = 0; tile < 10; tile++) {
                if (tile < 9) {
                    int k = (tile + 1) * 64 + kk_fix;
#pragma unroll
                    for (int j = 0; j < 16; j++) {
                        int e = tid + j * 256, n = e >> 6;
                        pf[j] = (k < VSZ) ? g_ctx[n * VSZ + k] : h1r[n * HD + (k - VSZ)];
                    }
                }
                const float* W = sm + OFF_WS1 + cidx * WS_STR + tile * 64;
                const float* U = US + buf * 4096 + ngrp * 256;
#pragma unroll
                for (int kk = 0; kk < 64; kk += 4) {
                    float4 w  = *(const float4*)(W + kk);
                    float4 x0 = *(const float4*)(U + kk);
                    float4 x1 = *(const float4*)(U + 64 + kk);
                    float4 x2 = *(const float4*)(U + 128 + kk);
                    float4 x3 = *(const float4*)(U + 192 + kk);
                    a0 = fmaf(x0.x, w.x, a0); a0 = fmaf(x0.y, w.y, a0); a0 = fmaf(x0.z, w.z, a0); a0 = fmaf(x0.w, w.w, a0);
                    a1 = fmaf(x1.x, w.x, a1); a1 = fmaf(x1.y, w.y, a1); a1 = fmaf(x1.z, w.z, a1); a1 = fmaf(x1.w, w.w, a1);
                    a2 = fmaf(x2.x, w.x, a2); a2 = fmaf(x2.y, w.y, a2); a2 = fmaf(x2.z, w.z, a2); a2 = fmaf(x2.w, w.w, a2);
                    a3 = fmaf(x3.x, w.x, a3); a3 = fmaf(x3.y, w.y, a3); a3 = fmaf(x3.z, w.z, a3); a3 = fmaf(x3.w, w.w, a3);
                }
                if (tile < 9) {
                    float* D = US + (buf ^ 1) * 4096;
#pragma unroll
                    for (int j = 0; j < 16; j++) D[tid + j * 256] = pf[j];
                    __syncthreads();
                    buf ^= 1;
                }
            }
            // assemble pre-activations, exchange, cell update
            float* GS = sm + OFF_GS;
            {
                const float* pr = g_pre1 + (size_t)(t * NB) * G1 + gcol;
                int n0 = ngrp * 4;
                GS[(n0 + 0) * 17 + cidx] = a0 + __ldg(pr + (size_t)(n0 + 0) * G1) + bias1;
                GS[(n0 + 1) * 17 + cidx] = a1 + __ldg(pr + (size_t)(n0 + 1) * G1) + bias1;
                GS[(n0 + 2) * 17 + cidx] = a2 + __ldg(pr + (size_t)(n0 + 2) * G1) + bias1;
                GS[(n0 + 3) * 17 + cidx] = a3 + __ldg(pr + (size_t)(n0 + 3) * G1) + bias1;
            }
            __syncthreads();
            {
                int n = tid >> 2, dl = tid & 3;
                float gi = GS[n * 17 + 0 + dl];
                float gf = GS[n * 17 + 4 + dl];
                float gg = GS[n * 17 + 8 + dl];
                float go = GS[n * 17 + 12 + dl];
                int idx = n * HD + d0 + dl;
                float c = sigf(gf) * g_c1[idx] + sigf(gi) * tanhf(gg);
                g_c1[idx] = c;
                h1w[idx] = sigf(go) * tanhf(c);
            }
        }
        gbar();

        // =============== PHASE B: gates2 + cell2 ===============
        {
            const float* h1w = g_h1[(t + 1) & 1];
            const float* h2r = g_h2[t & 1];
            float* h2w = g_h2[(t + 1) & 1];
            float acc = 0.f;
            float pf[4];
            {
                int k = kk_fix;
#pragma unroll
                for (int j = 0; j < 4; j++) {
                    int e = tid + j * 256, nn = e >> 6;
                    pf[j] = (k < HD) ? h1w[(nB0 + nn) * HD + k]
                                     : h2r[(nB0 + nn) * KSZ + (k - HD)];
                }
#pragma unroll
                for (int j = 0; j < 4; j++) US[tid + j * 256] = pf[j];
            }
            __syncthreads();
            int buf = 0;
            for (int tile = 0; tile < 10; tile++) {
                if (tile < 9) {
                    int k = (tile + 1) * 64 + kk_fix;
#pragma unroll
                    for (int j = 0; j < 4; j++) {
                        int e = tid + j * 256, nn = e >> 6;
                        pf[j] = (k < HD) ? h1w[(nB0 + nn) * HD + k]
                                         : h2r[(nB0 + nn) * KSZ + (k - HD)];
                    }
                }
                const float* W = sm + OFF_WS2 + cidx * WS_STR + tile * 64;
                const float* U = US + buf * 1024 + ngrp * 64;
#pragma unroll
                for (int kk = 0; kk < 64; kk += 4) {
                    float4 w = *(const float4*)(W + kk);
                    float4 x = *(const float4*)(U + kk);
                    acc = fmaf(x.x, w.x, acc); acc = fmaf(x.y, w.y, acc);
                    acc = fmaf(x.z, w.z, acc); acc = fmaf(x.w, w.w, acc);
                }
                if (tile < 9) {
                    float* D = US + (buf ^ 1) * 1024;
#pragma unroll
                    for (int j = 0; j < 4; j++) D[tid + j * 256] = pf[j];
                    __syncthreads();
                    buf ^= 1;
                }
            }
            float* GS2 = sm + OFF_GS2;
            GS2[ngrp * 17 + cidx] = acc + bias2;
            __syncthreads();
            if (tid < 64) {
                int ngl = tid >> 2, dl = tid & 3;
                int n = nB0 + ngl;
                float gi = GS2[ngl * 17 + 0 + dl];
                float gf = GS2[ngl * 17 + 4 + dl];
                float gg = GS2[ngl * 17 + 8 + dl];
                float go = GS2[ngl * 17 + 12 + dl];
                int idx = n * KSZ + d2base + dl;
                float c = sigf(gf) * g_c2[idx] + sigf(gi) * tanhf(gg);
                g_c2[idx] = c;
                float h = sigf(go) * tanhf(c);
                h2w[idx] = h;
                g_A[(size_t)(t * NB + n) * 256 + d2base + dl] = h;
            }
        }
        gbar();

        // =============== PHASE C: attention (64 blocks, one n each) ===============
        if (bi < NB) {
            const int n = bi;
            const float* h2w = g_h2[(t + 1) & 1];
            float* es = sm + OFF_ES;
            float* red = sm + OFF_RED;
            if (tid < KSZ) sm[OFF_H2S + tid] = h2w[n * KSZ + tid];
            __syncthreads();

            const float* ekn = enc_key + (size_t)n * TE * KSZ;
            const float4* h2s4 = (const float4*)(sm + OFF_H2S);
#pragma unroll
            for (int pass = 0; pass < 2; pass++) {
                int s = tid + pass * 256;
                const float4* row = (const float4*)(ekn + (size_t)s * KSZ);
                float e0 = 0.f, e1 = 0.f;
#pragma unroll 8
                for (int q = 0; q < 32; q += 2) {
                    float4 kv = row[q], hv = h2s4[q];
                    e0 += kv.x * hv.x + kv.y * hv.y + kv.z * hv.z + kv.w * hv.w;
                    float4 kv2 = row[q + 1], hv2 = h2s4[q + 1];
                    e1 += kv2.x * hv2.x + kv2.y * hv2.y + kv2.z * hv2.z + kv2.w * hv2.w;
                }
                es[s] = e0 + e1;
            }
            __syncthreads();

            float m = fmaxf(es[tid], es[tid + 256]);
#pragma unroll
            for (int o = 16; o; o >>= 1) m = fmaxf(m, __shfl_xor_sync(0xffffffffu, m, o));
            if (lane == 0) red[wrp] = m;
            __syncthreads();
            if (tid == 0) {
                float mm = red[0];
                for (int i = 1; i < 8; i++) mm = fmaxf(mm, red[i]);
                red[32] = mm;
            }
            __syncthreads();
            m = red[32];
            float p0 = (tid < len) ? expf(es[tid] - m) : 0.f;
            float p1 = (tid + 256 < len) ? expf(es[tid + 256] - m) : 0.f;
            float ssum = p0 + p1;
#pragma unroll
            for (int o = 16; o; o >>= 1) ssum += __shfl_xor_sync(0xffffffffu, ssum, o);
            if (lane == 0) red[wrp] = ssum;
            __syncthreads();
            if (tid == 0) {
                float ss = 0.f;
                for (int i = 0; i < 8; i++) ss += red[i];
                red[33] = ss;
            }
            __syncthreads();
            const float inv = 1.f / red[33];
            const float a0v = p0 * inv, a1v = p1 * inv;
            float* ao = attn_out + ((size_t)n * TD + t) * TE;
            ao[tid] = a0v;
            ao[tid + 256] = a1v;
            es[tid] = a0v;
            es[tid + 256] = a1v;
            __syncthreads();

            {
                int k = tid & 127, sh = tid >> 7;
                const float* vv = values + ((size_t)n * TE + sh * 256) * VSZ + k;
                const float* ap = es + sh * 256;
                float accv = 0.f;
#pragma unroll 8
                for (int s = 0; s < 256; s++) accv = fmaf(ap[s], vv[(size_t)s * VSZ], accv);
                sm[OFF_CTXS + sh * 128 + k] = accv;
            }
            __syncthreads();
            if (tid < VSZ) {
                float cv = sm[OFF_CTXS + tid] + sm[OFF_CTXS + 128 + tid];
                g_ctx[n * VSZ + tid] = cv;
                g_A[(size_t)(t * NB + n) * 256 + KSZ + tid] = cv;
            }
        }
        gbar();
    }
}

// ---------------- final logits GEMM: out = A[6336,256] @ Wout^T + bout (tf32) -----
__global__ __launch_bounds__(256) void out_gemm(const float* __restrict__ B,
                                                const float* __restrict__ bout,
                                                float* __restrict__ out)
{
    __shared__ float As[128][36];
    __shared__ float Bs[128][36];
    const int tid = threadIdx.x;
    const int lane = tid & 31;
    const int warp = tid >> 5;
    const int wm = warp & 1;
    const int wn = warp >> 1;
    const int mBase = blockIdx.y * 128;
    const int nBase = blockIdx.x * 128;

    float acc[4][4][4];
#pragma unroll
    for (int i = 0; i < 4; i++)
#pragma unroll
        for (int j = 0; j < 4; j++)
#pragma unroll
            for (int q = 0; q < 4; q++) acc[i][j][q] = 0.f;

    const int lr = tid >> 3;
    const int kq = (tid & 7) * 4;

    for (int k0 = 0; k0 < 256; k0 += 32) {
#pragma unroll
        for (int p = 0; p < 4; p++) {
            int row = lr + p * 32;
            float4 va = *(const float4*)(g_A + (size_t)(mBase + row) * 256 + k0 + kq);
            float4 vb = *(const float4*)(B + (size_t)(nBase + row) * 256 + k0 + kq);
            va.x = tf32r(va.x); va.y = tf32r(va.y); va.z = tf32r(va.z); va.w = tf32r(va.w);
            vb.x = tf32r(vb.x); vb.y = tf32r(vb.y); vb.z = tf32r(vb.z); vb.w = tf32r(vb.w);
            *(float4*)&As[row][kq] = va;
            *(float4*)&Bs[row][kq] = vb;
        }
        __syncthreads();
#pragma unroll
        for (int ks = 0; ks < 4; ks++) {
            unsigned af[4][4], bf[4][2];
            const int ar = wm * 64 + (lane >> 2);
            const int ac = ks * 8 + (lane & 3);
#pragma unroll
            for (int mt = 0; mt < 4; mt++) {
                af[mt][0] = __float_as_uint(As[ar + mt * 16][ac]);
                af[mt][1] = __float_as_uint(As[ar + mt * 16 + 8][ac]);
                af[mt][2] = __float_as_uint(As[ar + mt * 16][ac + 4]);
                af[mt][3] = __float_as_uint(As[ar + mt * 16 + 8][ac + 4]);
            }
            const int br = wn * 32 + (lane >> 2);
#pragma unroll
            for (int nt = 0; nt < 4; nt++) {
                bf[nt][0] = __float_as_uint(Bs[br + nt * 8][ac]);
                bf[nt][1] = __float_as_uint(Bs[br + nt * 8][ac + 4]);
            }
#pragma unroll
            for (int mt = 0; mt < 4; mt++)
#pragma unroll
                for (int nt = 0; nt < 4; nt++)
                    asm volatile(
                        "mma.sync.aligned.m16n8k8.row.col.f32.tf32.tf32.f32 "
                        "{%0,%1,%2,%3},{%4,%5,%6,%7},{%8,%9},{%0,%1,%2,%3};\n"
                        : "+f"(acc[mt][nt][0]), "+f"(acc[mt][nt][1]),
                          "+f"(acc[mt][nt][2]), "+f"(acc[mt][nt][3])
                        : "r"(af[mt][0]), "r"(af[mt][1]), "r"(af[mt][2]), "r"(af[mt][3]),
                          "r"(bf[nt][0]), "r"(bf[nt][1]));
        }
        __syncthreads();
    }

#pragma unroll
    for (int mt = 0; mt < 4; mt++) {
#pragma unroll
        for (int half = 0; half < 2; half++) {
            int gRow = mBase + wm * 64 + mt * 16 + (lane >> 2) + half * 8;
            if (gRow < MROWS) {
                int outRow = (gRow & 63) * TD + (gRow >> 6);
                float* op = out + (size_t)outRow * VOC + nBase + wn * 32 + (lane & 3) * 2;
#pragma unroll
                for (int nt = 0; nt < 4; nt++) {
                    int bc = nBase + wn * 32 + nt * 8 + (lane & 3) * 2;
                    float2 v;
                    v.x = acc[mt][nt][half * 2 + 0] + bout[bc];
                    v.y = acc[mt][nt][half * 2 + 1] + bout[bc + 1];
                    __stcs(reinterpret_cast<float2*>(op + nt * 8), v);
                }
            }
        }
    }
}

// ---------------- launch ----------------
extern "C" void kernel_launch(void* const* d_in, const int* in_sizes, int n_in,
                              void* d_out, int out_size)
{
    const float* enc_key   = (const float*)d_in[0];
    const float* values    = (const float*)d_in[1];
    const int*   lens      = (const int*)d_in[2];
    const int*   text      = (const int*)d_in[3];
    const float* embedding = (const float*)d_in[4];
    const float* Wih1 = (const float*)d_in[5];
    const float* Whh1 = (const float*)d_in[6];
    const float* bih1 = (const float*)d_in[7];
    const float* bhh1 = (const float*)d_in[8];
    const float* Wih2 = (const float*)d_in[9];
    const float* Whh2 = (const float*)d_in[10];
    const float* bih2 = (const float*)d_in[11];
    const float* bhh2 = (const float*)d_in[12];
    const float* Wout = (const float*)d_in[13];
    const float* bout = (const float*)d_in[14];

    float* out = (float*)d_out;
    float* attn_out = out + (size_t)MROWS * VOC;

    cudaFuncSetAttribute((const void*)decode_kernel,
                         cudaFuncAttributeMaxDynamicSharedMemorySize, SMEM_BYTES);

    setup_kernel<<<2048, 256>>>(bih1, bhh1, bih2, bhh2, embedding, text);
    pre_gemm<<<dim3(G1 / 128, MPAD / 128), 256>>>(Wih1);
    decode_kernel<<<NBLK, 256, SMEM_BYTES>>>(enc_key, values, lens,
                                             Wih1, Whh1, Wih2, Whh2, attn_out);
    out_gemm<<<dim3(VOC / 128, MPAD / 128), 256>>>(Wout, bout, out);
}

// round 6
// speedup vs baseline: 2.4563x; 1.5087x over previous
#include <cuda_runtime.h>
#include <math.h>

#define NB   64
#define TE   512
#define KSZ  128
#define VSZ  128
#define HD   512
#define TD   99
#define VOC  32000
#define MROWS 6336
#define MPAD  6400
#define NBLK  128
#define G1   2048
#define G2   512
#define KREC 640            // serial K for both gate GEMMs

// ---------------- static device scratch ----------------
__device__ float g_embs[(size_t)MPAD * HD];          // 13.1 MB
__device__ float g_pre1[(size_t)MPAD * G1];          // 52.4 MB (emb part of gates1)
__device__ float g_A[(size_t)MPAD * 256];            // [t*64+n][h2|ctx]
__device__ float g_h1[2][NB * HD];
__device__ float g_c1[NB * HD];
__device__ float g_h2[2][NB * KSZ];
__device__ float g_c2[NB * KSZ];
__device__ float g_ctx[NB * VSZ];
__device__ float g_b1[G1];
__device__ float g_b2[G2];
__device__ int g_bar_cnt = 0;
__device__ volatile int g_bar_gen = 0;

__device__ __forceinline__ float sigf(float x) { return 1.f / (1.f + expf(-x)); }

__device__ __forceinline__ float tf32r(float x) {
    asm("cvt.rna.tf32.f32 %0, %0;" : "+f"(x));
    return x;
}

// grid-wide barrier across NBLK resident blocks
__device__ __forceinline__ void gbar() {
    __syncthreads();
    if (threadIdx.x == 0) {
        int gen = g_bar_gen;
        __threadfence();
        if (atomicAdd(&g_bar_cnt, 1) == NBLK - 1) {
            g_bar_cnt = 0;
            __threadfence();
            g_bar_gen = gen + 1;
        } else {
            while (g_bar_gen == gen) __nanosleep(64);
            __threadfence();
        }
    }
    __syncthreads();
}

// ---------------- setup: states, biases, embedding gather ----------------
__global__ void setup_kernel(const float* __restrict__ bih1, const float* __restrict__ bhh1,
                             const float* __restrict__ bih2, const float* __restrict__ bhh2,
                             const float* __restrict__ embedding, const int* __restrict__ text)
{
    const long S_B1 = G1, S_B2 = G2;
    const long S_H1 = 2L * NB * HD, S_C1 = NB * HD;
    const long S_H2 = 2L * NB * KSZ, S_C2 = NB * KSZ, S_CTX = NB * VSZ;
    const long S_EMB = (long)MPAD * HD;
    const long S_APAD = (long)(MPAD - MROWS) * 256;
    const long total = S_B1 + S_B2 + S_H1 + S_C1 + S_H2 + S_C2 + S_CTX + S_EMB + S_APAD;
    const long stride = (long)gridDim.x * blockDim.x;

    for (long idx = (long)blockIdx.x * blockDim.x + threadIdx.x; idx < total; idx += stride) {
        long i = idx;
        if (i < S_B1) { g_b1[i] = bih1[i] + bhh1[i]; continue; } i -= S_B1;
        if (i < S_B2) { g_b2[i] = bih2[i] + bhh2[i]; continue; } i -= S_B2;
        if (i < S_H1) { ((float*)g_h1)[i] = 0.f; continue; } i -= S_H1;
        if (i < S_C1) { g_c1[i] = 0.f; continue; } i -= S_C1;
        if (i < S_H2) { ((float*)g_h2)[i] = 0.f; continue; } i -= S_H2;
        if (i < S_C2) { g_c2[i] = 0.f; continue; } i -= S_C2;
        if (i < S_CTX){ g_ctx[i] = 0.f; continue; } i -= S_CTX;
        if (i < S_EMB) {
            long row = i / HD; int d = (int)(i % HD);
            if (row < MROWS) {
                int t = (int)(row >> 6), n = (int)(row & 63);
                int tok = text[n * 100 + t];
                g_embs[i] = embedding[(size_t)tok * HD + d];
            } else g_embs[i] = 0.f;
            continue;
        }
        i -= S_EMB;
        g_A[(size_t)MROWS * 256 + i] = 0.f;
    }
}

// ---------------- tf32 GEMM: g_pre1[6400,2048] = g_embs[6400,512] @ Wih1[:, :512]^T --
__global__ __launch_bounds__(256) void pre_gemm(const float* __restrict__ B)
{
    __shared__ float As[128][36];
    __shared__ float Bs[128][36];
    const int tid = threadIdx.x;
    const int lane = tid & 31;
    const int warp = tid >> 5;
    const int wm = warp & 1;
    const int wn = warp >> 1;
    const int mBase = blockIdx.y * 128;
    const int nBase = blockIdx.x * 128;

    float acc[4][4][4];
#pragma unroll
    for (int i = 0; i < 4; i++)
#pragma unroll
        for (int j = 0; j < 4; j++)
#pragma unroll
            for (int q = 0; q < 4; q++) acc[i][j][q] = 0.f;

    const int lr = tid >> 3;
    const int kq = (tid & 7) * 4;

    for (int k0 = 0; k0 < 512; k0 += 32) {
#pragma unroll
        for (int p = 0; p < 4; p++) {
            int row = lr + p * 32;
            float4 va = *(const float4*)(g_embs + (size_t)(mBase + row) * 512 + k0 + kq);
            float4 vb = *(const float4*)(B + (size_t)(nBase + row) * 640 + k0 + kq);
            va.x = tf32r(va.x); va.y = tf32r(va.y); va.z = tf32r(va.z); va.w = tf32r(va.w);
            vb.x = tf32r(vb.x); vb.y = tf32r(vb.y); vb.z = tf32r(vb.z); vb.w = tf32r(vb.w);
            *(float4*)&As[row][kq] = va;
            *(float4*)&Bs[row][kq] = vb;
        }
        __syncthreads();
#pragma unroll
        for (int ks = 0; ks < 4; ks++) {
            unsigned af[4][4], bf[4][2];
            const int ar = wm * 64 + (lane >> 2);
            const int ac = ks * 8 + (lane & 3);
#pragma unroll
            for (int mt = 0; mt < 4; mt++) {
                af[mt][0] = __float_as_uint(As[ar + mt * 16][ac]);
                af[mt][1] = __float_as_uint(As[ar + mt * 16 + 8][ac]);
                af[mt][2] = __float_as_uint(As[ar + mt * 16][ac + 4]);
                af[mt][3] = __float_as_uint(As[ar + mt * 16 + 8][ac + 4]);
            }
            const int br = wn * 32 + (lane >> 2);
#pragma unroll
            for (int nt = 0; nt < 4; nt++) {
                bf[nt][0] = __float_as_uint(Bs[br + nt * 8][ac]);
                bf[nt][1] = __float_as_uint(Bs[br + nt * 8][ac + 4]);
            }
#pragma unroll
            for (int mt = 0; mt < 4; mt++)
#pragma unroll
                for (int nt = 0; nt < 4; nt++)
                    asm volatile(
                        "mma.sync.aligned.m16n8k8.row.col.f32.tf32.tf32.f32 "
                        "{%0,%1,%2,%3},{%4,%5,%6,%7},{%8,%9},{%0,%1,%2,%3};\n"
                        : "+f"(acc[mt][nt][0]), "+f"(acc[mt][nt][1]),
                          "+f"(acc[mt][nt][2]), "+f"(acc[mt][nt][3])
                        : "r"(af[mt][0]), "r"(af[mt][1]), "r"(af[mt][2]), "r"(af[mt][3]),
                          "r"(bf[nt][0]), "r"(bf[nt][1]));
        }
        __syncthreads();
    }

#pragma unroll
    for (int mt = 0; mt < 4; mt++)
#pragma unroll
        for (int half = 0; half < 2; half++) {
            int gRow = mBase + wm * 64 + mt * 16 + (lane >> 2) + half * 8;
            float* op = g_pre1 + (size_t)gRow * G1 + nBase + wn * 32 + (lane & 3) * 2;
#pragma unroll
            for (int nt = 0; nt < 4; nt++) {
                float2 v;
                v.x = acc[mt][nt][half * 2 + 0];
                v.y = acc[mt][nt][half * 2 + 1];
                *reinterpret_cast<float2*>(op + nt * 8) = v;
            }
        }
}

// ---------------- persistent decode kernel ----------------
// smem layout (floats)
#define OFF_WS1  0
#define WS_STR   644
#define OFF_WS2  (16 * WS_STR)                 // 10304
#define OFF_US   (2 * 16 * WS_STR)             // 20608
#define OFF_GS   (OFF_US + 8192)               // 28800
#define OFF_GS2  (OFF_GS + 64 * 17)            // 29888
#define OFF_ES   (OFF_GS2 + 16 * 17)           // 30160
#define OFF_H2S  (OFF_ES + 512)                // 30672
#define OFF_RED  (OFF_H2S + 128)               // 30800
#define OFF_CTXS (OFF_RED + 64)                // 30864
#define SMEM_FLOATS (OFF_CTXS + 256)           // 31120
#define SMEM_BYTES  (SMEM_FLOATS * 4)

__global__ __launch_bounds__(256, 1) void decode_kernel(
    const float* __restrict__ enc_key, const float* __restrict__ values,
    const int* __restrict__ lens,
    const float* __restrict__ Wih1, const float* __restrict__ Whh1,
    const float* __restrict__ Wih2, const float* __restrict__ Whh2,
    float* __restrict__ attn_out)
{
    extern __shared__ float sm[];
    const int bi = blockIdx.x;
    const int tid = threadIdx.x;
    const int lane = tid & 31;
    const int wrp = tid >> 5;

    // ---- phase-A role constants: block owns d in [d0, d0+4) of h1 ----
    const int d0 = bi * 4;
    const int cidx = tid & 15;          // col within 16-col slice: gate*4+dl
    const int ngrp = tid >> 4;          // 16 batch groups of 4
    const int gateA = cidx >> 2, dlA = cidx & 3;
    const int gcol = gateA * HD + d0 + dlA;

    // ---- phase-B role constants: block owns 4 d2 x 16 batches ----
    const int d2base = (bi >> 2) * 4;
    const int nq = bi & 3;
    const int gateB = cidx >> 2, dlB = cidx & 3;
    const int g2col = gateB * KSZ + d2base + dlB;
    const int nB0 = nq * 16;

    // load weight slices into smem (once)
    for (int i = tid; i < 16 * KREC; i += 256) {
        int c = i / KREC, k = i % KREC;
        int g = (c >> 2) * HD + d0 + (c & 3);
        float w = (k < VSZ) ? Wih1[(size_t)g * (HD + VSZ) + HD + k]
                            : Whh1[(size_t)g * HD + (k - VSZ)];
        sm[OFF_WS1 + c * WS_STR + k] = w;
    }
    for (int i = tid; i < 16 * KREC; i += 256) {
        int c = i / KREC, k = i % KREC;
        int g = (c >> 2) * KSZ + d2base + (c & 3);
        float w = (k < HD) ? Wih2[(size_t)g * HD + k]
                           : Whh2[(size_t)g * KSZ + (k - HD)];
        sm[OFF_WS2 + c * WS_STR + k] = w;
    }
    __syncthreads();

    const float bias1 = g_b1[gcol];
    const float bias2 = g_b2[g2col];
    const int len = (bi < NB) ? lens[bi] : 0;
    const int kk_fix = tid & 63;
    float* US = sm + OFF_US;

    for (int t = 0; t < TD; t++) {
        // =============== PHASE A: gates1 + cell1 ===============
        {
            const float* h1r = g_h1[t & 1];
            float* h1w = g_h1[(t + 1) & 1];
            float a0 = 0.f, a1 = 0.f, a2 = 0.f, a3 = 0.f;
            float pf[16];

            // prefetch tile 0
            {
                int k = kk_fix;
#pragma unroll
                for (int j = 0; j < 16; j++) {
                    int e = tid + j * 256, n = e >> 6;
                    pf[j] = (k < VSZ) ? g_ctx[n * VSZ + k] : h1r[n * HD + (k - VSZ)];
                }
#pragma unroll
                for (int j = 0; j < 16; j++) US[tid + j * 256] = pf[j];
            }
            __syncthreads();
            int buf = 0;
            for (int tile = 0; tile < 10; tile++) {
                if (tile < 9) {
                    int k = (tile + 1) * 64 + kk_fix;
#pragma unroll
                    for (int j = 0; j < 16; j++) {
                        int e = tid + j * 256, n = e >> 6;
                        pf[j] = (k < VSZ) ? g_ctx[n * VSZ + k] : h1r[n * HD + (k - VSZ)];
                    }
                }
                const float* W = sm + OFF_WS1 + cidx * WS_STR + tile * 64;
                const float* U = US + buf * 4096 + ngrp * 256;
#pragma unroll
                for (int kk = 0; kk < 64; kk += 4) {
                    float4 w  = *(const float4*)(W + kk);
                    float4 x0 = *(const float4*)(U + kk);
                    float4 x1 = *(const float4*)(U + 64 + kk);
                    float4 x2 = *(const float4*)(U + 128 + kk);
                    float4 x3 = *(const float4*)(U + 192 + kk);
                    a0 = fmaf(x0.x, w.x, a0); a0 = fmaf(x0.y, w.y, a0); a0 = fmaf(x0.z, w.z, a0); a0 = fmaf(x0.w, w.w, a0);
                    a1 = fmaf(x1.x, w.x, a1); a1 = fmaf(x1.y, w.y, a1); a1 = fmaf(x1.z, w.z, a1); a1 = fmaf(x1.w, w.w, a1);
                    a2 = fmaf(x2.x, w.x, a2); a2 = fmaf(x2.y, w.y, a2); a2 = fmaf(x2.z, w.z, a2); a2 = fmaf(x2.w, w.w, a2);
                    a3 = fmaf(x3.x, w.x, a3); a3 = fmaf(x3.y, w.y, a3); a3 = fmaf(x3.z, w.z, a3); a3 = fmaf(x3.w, w.w, a3);
                }
                if (tile < 9) {
                    float* D = US + (buf ^ 1) * 4096;
#pragma unroll
                    for (int j = 0; j < 16; j++) D[tid + j * 256] = pf[j];
                    __syncthreads();
                    buf ^= 1;
                }
            }
            // assemble pre-activations, exchange, cell update
            float* GS = sm + OFF_GS;
            {
                const float* pr = g_pre1 + (size_t)(t * NB) * G1 + gcol;
                int n0 = ngrp * 4;
                GS[(n0 + 0) * 17 + cidx] = a0 + __ldg(pr + (size_t)(n0 + 0) * G1) + bias1;
                GS[(n0 + 1) * 17 + cidx] = a1 + __ldg(pr + (size_t)(n0 + 1) * G1) + bias1;
                GS[(n0 + 2) * 17 + cidx] = a2 + __ldg(pr + (size_t)(n0 + 2) * G1) + bias1;
                GS[(n0 + 3) * 17 + cidx] = a3 + __ldg(pr + (size_t)(n0 + 3) * G1) + bias1;
            }
            __syncthreads();
            {
                int n = tid >> 2, dl = tid & 3;
                float gi = GS[n * 17 + 0 + dl];
                float gf = GS[n * 17 + 4 + dl];
                float gg = GS[n * 17 + 8 + dl];
                float go = GS[n * 17 + 12 + dl];
                int idx = n * HD + d0 + dl;
                float c = sigf(gf) * g_c1[idx] + sigf(gi) * tanhf(gg);
                g_c1[idx] = c;
                h1w[idx] = sigf(go) * tanhf(c);
            }
        }
        gbar();

        // =============== PHASE B: gates2 + cell2 ===============
        {
            const float* h1w = g_h1[(t + 1) & 1];
            const float* h2r = g_h2[t & 1];
            float* h2w = g_h2[(t + 1) & 1];
            float acc = 0.f;
            float pf[4];
            {
                int k = kk_fix;
#pragma unroll
                for (int j = 0; j < 4; j++) {
                    int e = tid + j * 256, nn = e >> 6;
                    pf[j] = (k < HD) ? h1w[(nB0 + nn) * HD + k]
                                     : h2r[(nB0 + nn) * KSZ + (k - HD)];
                }
#pragma unroll
                for (int j = 0; j < 4; j++) US[tid + j * 256] = pf[j];
            }
            __syncthreads();
            int buf = 0;
            for (int tile = 0; tile < 10; tile++) {
                if (tile < 9) {
                    int k = (tile + 1) * 64 + kk_fix;
#pragma unroll
                    for (int j = 0; j < 4; j++) {
                        int e = tid + j * 256, nn = e >> 6;
                        pf[j] = (k < HD) ? h1w[(nB0 + nn) * HD + k]
                                         : h2r[(nB0 + nn) * KSZ + (k - HD)];
                    }
                }
                const float* W = sm + OFF_WS2 + cidx * WS_STR + tile * 64;
                const float* U = US + buf * 1024 + ngrp * 64;
#pragma unroll
                for (int kk = 0; kk < 64; kk += 4) {
                    float4 w = *(const float4*)(W + kk);
                    float4 x = *(const float4*)(U + kk);
                    acc = fmaf(x.x, w.x, acc); acc = fmaf(x.y, w.y, acc);
                    acc = fmaf(x.z, w.z, acc); acc = fmaf(x.w, w.w, acc);
                }
                if (tile < 9) {
                    float* D = US + (buf ^ 1) * 1024;
#pragma unroll
                    for (int j = 0; j < 4; j++) D[tid + j * 256] = pf[j];
                    __syncthreads();
                    buf ^= 1;
                }
            }
            float* GS2 = sm + OFF_GS2;
            GS2[ngrp * 17 + cidx] = acc + bias2;
            __syncthreads();
            if (tid < 64) {
                int ngl = tid >> 2, dl = tid & 3;
                int n = nB0 + ngl;
                float gi = GS2[ngl * 17 + 0 + dl];
                float gf = GS2[ngl * 17 + 4 + dl];
                float gg = GS2[ngl * 17 + 8 + dl];
                float go = GS2[ngl * 17 + 12 + dl];
                int idx = n * KSZ + d2base + dl;
                float c = sigf(gf) * g_c2[idx] + sigf(gi) * tanhf(gg);
                g_c2[idx] = c;
                float h = sigf(go) * tanhf(c);
                h2w[idx] = h;
                g_A[(size_t)(t * NB + n) * 256 + d2base + dl] = h;
            }
        }
        gbar();

        // =============== PHASE C: attention (64 blocks, one n each) ===============
        if (bi < NB) {
            const int n = bi;
            const float* h2w = g_h2[(t + 1) & 1];
            float* es = sm + OFF_ES;
            float* red = sm + OFF_RED;
            if (tid < KSZ) sm[OFF_H2S + tid] = h2w[n * KSZ + tid];
            __syncthreads();

            const float* ekn = enc_key + (size_t)n * TE * KSZ;
            const float4* h2s4 = (const float4*)(sm + OFF_H2S);
#pragma unroll
            for (int pass = 0; pass < 2; pass++) {
                int s = tid + pass * 256;
                const float4* row = (const float4*)(ekn + (size_t)s * KSZ);
                float e0 = 0.f, e1 = 0.f;
#pragma unroll 8
                for (int q = 0; q < 32; q += 2) {
                    float4 kv = row[q], hv = h2s4[q];
                    e0 += kv.x * hv.x + kv.y * hv.y + kv.z * hv.z + kv.w * hv.w;
                    float4 kv2 = row[q + 1], hv2 = h2s4[q + 1];
                    e1 += kv2.x * hv2.x + kv2.y * hv2.y + kv2.z * hv2.z + kv2.w * hv2.w;
                }
                es[s] = e0 + e1;
            }
            __syncthreads();

            float m = fmaxf(es[tid], es[tid + 256]);
#pragma unroll
            for (int o = 16; o; o >>= 1) m = fmaxf(m, __shfl_xor_sync(0xffffffffu, m, o));
            if (lane == 0) red[wrp] = m;
            __syncthreads();
            if (tid == 0) {
                float mm = red[0];
                for (int i = 1; i < 8; i++) mm = fmaxf(mm, red[i]);
                red[32] = mm;
            }
            __syncthreads();
            m = red[32];
            float p0 = (tid < len) ? expf(es[tid] - m) : 0.f;
            float p1 = (tid + 256 < len) ? expf(es[tid + 256] - m) : 0.f;
            float ssum = p0 + p1;
#pragma unroll
            for (int o = 16; o; o >>= 1) ssum += __shfl_xor_sync(0xffffffffu, ssum, o);
            if (lane == 0) red[wrp] = ssum;
            __syncthreads();
            if (tid == 0) {
                float ss = 0.f;
                for (int i = 0; i < 8; i++) ss += red[i];
                red[33] = ss;
            }
            __syncthreads();
            const float inv = 1.f / red[33];
            const float a0v = p0 * inv, a1v = p1 * inv;
            float* ao = attn_out + ((size_t)n * TD + t) * TE;
            ao[tid] = a0v;
            ao[tid + 256] = a1v;
            es[tid] = a0v;
            es[tid + 256] = a1v;
            __syncthreads();

            {
                int k = tid & 127, sh = tid >> 7;
                const float* vv = values + ((size_t)n * TE + sh * 256) * VSZ + k;
                const float* ap = es + sh * 256;
                float accv = 0.f;
#pragma unroll 8
                for (int s = 0; s < 256; s++) accv = fmaf(ap[s], vv[(size_t)s * VSZ], accv);
                sm[OFF_CTXS + sh * 128 + k] = accv;
            }
            __syncthreads();
            if (tid < VSZ) {
                float cv = sm[OFF_CTXS + tid] + sm[OFF_CTXS + 128 + tid];
                g_ctx[n * VSZ + tid] = cv;
                g_A[(size_t)(t * NB + n) * 256 + KSZ + tid] = cv;
            }
        }
        gbar();
    }
}

// ---------------- final logits GEMM: out = A[6336,256] @ Wout^T + bout (tf32) -----
__global__ __launch_bounds__(256) void out_gemm(const float* __restrict__ B,
                                                const float* __restrict__ bout,
                                                float* __restrict__ out)
{
    __shared__ float As[128][36];
    __shared__ float Bs[128][36];
    const int tid = threadIdx.x;
    const int lane = tid & 31;
    const int warp = tid >> 5;
    const int wm = warp & 1;
    const int wn = warp >> 1;
    const int mBase = blockIdx.y * 128;
    const int nBase = blockIdx.x * 128;

    float acc[4][4][4];
#pragma unroll
    for (int i = 0; i < 4; i++)
#pragma unroll
        for (int j = 0; j < 4; j++)
#pragma unroll
            for (int q = 0; q < 4; q++) acc[i][j][q] = 0.f;

    const int lr = tid >> 3;
    const int kq = (tid & 7) * 4;

    for (int k0 = 0; k0 < 256; k0 += 32) {
#pragma unroll
        for (int p = 0; p < 4; p++) {
            int row = lr + p * 32;
            float4 va = *(const float4*)(g_A + (size_t)(mBase + row) * 256 + k0 + kq);
            float4 vb = *(const float4*)(B + (size_t)(nBase + row) * 256 + k0 + kq);
            va.x = tf32r(va.x); va.y = tf32r(va.y); va.z = tf32r(va.z); va.w = tf32r(va.w);
            vb.x = tf32r(vb.x); vb.y = tf32r(vb.y); vb.z = tf32r(vb.z); vb.w = tf32r(vb.w);
            *(float4*)&As[row][kq] = va;
            *(float4*)&Bs[row][kq] = vb;
        }
        __syncthreads();
#pragma unroll
        for (int ks = 0; ks < 4; ks++) {
            unsigned af[4][4], bf[4][2];
            const int ar = wm * 64 + (lane >> 2);
            const int ac = ks * 8 + (lane & 3);
#pragma unroll
            for (int mt = 0; mt < 4; mt++) {
                af[mt][0] = __float_as_uint(As[ar + mt * 16][ac]);
                af[mt][1] = __float_as_uint(As[ar + mt * 16 + 8][ac]);
                af[mt][2] = __float_as_uint(As[ar + mt * 16][ac + 4]);
                af[mt][3] = __float_as_uint(As[ar + mt * 16 + 8][ac + 4]);
            }
            const int br = wn * 32 + (lane >> 2);
#pragma unroll
            for (int nt = 0; nt < 4; nt++) {
                bf[nt][0] = __float_as_uint(Bs[br + nt * 8][ac]);
                bf[nt][1] = __float_as_uint(Bs[br + nt * 8][ac + 4]);
            }
#pragma unroll
            for (int mt = 0; mt < 4; mt++)
#pragma unroll
                for (int nt = 0; nt < 4; nt++)
                    asm volatile(
                        "mma.sync.aligned.m16n8k8.row.col.f32.tf32.tf32.f32 "
                        "{%0,%1,%2,%3},{%4,%5,%6,%7},{%8,%9},{%0,%1,%2,%3};\n"
                        : "+f"(acc[mt][nt][0]), "+f"(acc[mt][nt][1]),
                          "+f"(acc[mt][nt][2]), "+f"(acc[mt][nt][3])
                        : "r"(af[mt][0]), "r"(af[mt][1]), "r"(af[mt][2]), "r"(af[mt][3]),
                          "r"(bf[nt][0]), "r"(bf[nt][1]));
        }
        __syncthreads();
    }

#pragma unroll
    for (int mt = 0; mt < 4; mt++) {
#pragma unroll
        for (int half = 0; half < 2; half++) {
            int gRow = mBase + wm * 64 + mt * 16 + (lane >> 2) + half * 8;
            if (gRow < MROWS) {
                int outRow = (gRow & 63) * TD + (gRow >> 6);
                float* op = out + (size_t)outRow * VOC + nBase + wn * 32 + (lane & 3) * 2;
#pragma unroll
                for (int nt = 0; nt < 4; nt++) {
                    int bc = nBase + wn * 32 + nt * 8 + (lane & 3) * 2;
                    float2 v;
                    v.x = acc[mt][nt][half * 2 + 0] + bout[bc];
                    v.y = acc[mt][nt][half * 2 + 1] + bout[bc + 1];
                    __stcs(reinterpret_cast<float2*>(op + nt * 8), v);
                }
            }
        }
    }
}

// ---------------- launch ----------------
extern "C" void kernel_launch(void* const* d_in, const int* in_sizes, int n_in,
                              void* d_out, int out_size)
{
    const float* enc_key   = (const float*)d_in[0];
    const float* values    = (const float*)d_in[1];
    const int*   lens      = (const int*)d_in[2];
    const int*   text      = (const int*)d_in[3];
    const float* embedding = (const float*)d_in[4];
    const float* Wih1 = (const float*)d_in[5];
    const float* Whh1 = (const float*)d_in[6];
    const float* bih1 = (const float*)d_in[7];
    const float* bhh1 = (const float*)d_in[8];
    const float* Wih2 = (const float*)d_in[9];
    const float* Whh2 = (const float*)d_in[10];
    const float* bih2 = (const float*)d_in[11];
    const float* bhh2 = (const float*)d_in[12];
    const float* Wout = (const float*)d_in[13];
    const float* bout = (const float*)d_in[14];

    float* out = (float*)d_out;
    float* attn_out = out + (size_t)MROWS * VOC;

    cudaFuncSetAttribute((const void*)decode_kernel,
                         cudaFuncAttributeMaxDynamicSharedMemorySize, SMEM_BYTES);

    setup_kernel<<<2048, 256>>>(bih1, bhh1, bih2, bhh2, embedding, text);
    pre_gemm<<<dim3(G1 / 128, MPAD / 128), 256>>>(Wih1);
    decode_kernel<<<NBLK, 256, SMEM_BYTES>>>(enc_key, values, lens,
                                             Wih1, Whh1, Wih2, Whh2, attn_out);
    out_gemm<<<dim3(VOC / 128, MPAD / 128), 256>>>(Wout, bout, out);
}

// round 7
// speedup vs baseline: 2.5295x; 1.0298x over previous
#include <cuda_runtime.h>
#include <math.h>

#define NB   64
#define TE   512
#define KSZ  128
#define VSZ  128
#define HD   512
#define TD   99
#define VOC  32000
#define MROWS 6336
#define MPAD  6400
#define NBLK  128
#define G1   2048
#define G2   512
#define KREC 640            // serial K for both gate GEMMs

// ---------------- static device scratch ----------------
__device__ float g_embs[(size_t)MPAD * HD];          // 13.1 MB
__device__ float g_pre1[(size_t)MPAD * G1];          // 52.4 MB (emb part of gates1)
__device__ float g_A[(size_t)MPAD * 256];            // [t*64+n][h2|ctx]
__device__ float g_h1[2][NB * HD];
__device__ float g_c1[NB * HD];
__device__ float g_h2[2][NB * KSZ];
__device__ float g_c2[NB * KSZ];
__device__ float g_ctx[NB * VSZ];
__device__ float g_b1[G1];
__device__ float g_b2[G2];
__device__ int g_bar_cnt = 0;
__device__ volatile int g_bar_gen = 0;

__device__ __forceinline__ float sigf(float x) { return 1.f / (1.f + expf(-x)); }

__device__ __forceinline__ float tf32r(float x) {
    asm("cvt.rna.tf32.f32 %0, %0;" : "+f"(x));
    return x;
}

// packed dual-fp32 FMA (sm_100+): d.lo = a.lo*b.lo + d.lo ; d.hi = a.hi*b.hi + d.hi
#define FMA2(d, a, b) asm("fma.rn.f32x2 %0, %1, %2, %0;" : "+l"(d) : "l"(a), "l"(b))

__device__ __forceinline__ float f2lo(unsigned long long u) {
    return __uint_as_float((unsigned)u);
}
__device__ __forceinline__ float f2hi(unsigned long long u) {
    return __uint_as_float((unsigned)(u >> 32));
}

// grid-wide barrier across NBLK resident blocks
__device__ __forceinline__ void gbar() {
    __syncthreads();
    if (threadIdx.x == 0) {
        int gen = g_bar_gen;
        __threadfence();
        if (atomicAdd(&g_bar_cnt, 1) == NBLK - 1) {
            g_bar_cnt = 0;
            __threadfence();
            g_bar_gen = gen + 1;
        } else {
            while (g_bar_gen == gen) __nanosleep(64);
            __threadfence();
        }
    }
    __syncthreads();
}

// ---------------- setup: states, biases, embedding gather ----------------
__global__ void setup_kernel(const float* __restrict__ bih1, const float* __restrict__ bhh1,
                             const float* __restrict__ bih2, const float* __restrict__ bhh2,
                             const float* __restrict__ embedding, const int* __restrict__ text)
{
    const long S_B1 = G1, S_B2 = G2;
    const long S_H1 = 2L * NB * HD, S_C1 = NB * HD;
    const long S_H2 = 2L * NB * KSZ, S_C2 = NB * KSZ, S_CTX = NB * VSZ;
    const long S_EMB = (long)MPAD * HD;
    const long S_APAD = (long)(MPAD - MROWS) * 256;
    const long total = S_B1 + S_B2 + S_H1 + S_C1 + S_H2 + S_C2 + S_CTX + S_EMB + S_APAD;
    const long stride = (long)gridDim.x * blockDim.x;

    for (long idx = (long)blockIdx.x * blockDim.x + threadIdx.x; idx < total; idx += stride) {
        long i = idx;
        if (i < S_B1) { g_b1[i] = bih1[i] + bhh1[i]; continue; } i -= S_B1;
        if (i < S_B2) { g_b2[i] = bih2[i] + bhh2[i]; continue; } i -= S_B2;
        if (i < S_H1) { ((float*)g_h1)[i] = 0.f; continue; } i -= S_H1;
        if (i < S_C1) { g_c1[i] = 0.f; continue; } i -= S_C1;
        if (i < S_H2) { ((float*)g_h2)[i] = 0.f; continue; } i -= S_H2;
        if (i < S_C2) { g_c2[i] = 0.f; continue; } i -= S_C2;
        if (i < S_CTX){ g_ctx[i] = 0.f; continue; } i -= S_CTX;
        if (i < S_EMB) {
            long row = i / HD; int d = (int)(i % HD);
            if (row < MROWS) {
                int t = (int)(row >> 6), n = (int)(row & 63);
                int tok = text[n * 100 + t];
                g_embs[i] = embedding[(size_t)tok * HD + d];
            } else g_embs[i] = 0.f;
            continue;
        }
        i -= S_EMB;
        g_A[(size_t)MROWS * 256 + i] = 0.f;
    }
}

// interleaved smem column index: within each 8-col mma k-group, col w -> 2*(w&3)+(w>>2)
// so a thread's fragment pair (c, c+4) is contiguous (one float2 LDS)
__device__ __forceinline__ int ilv_base(int kq) {
    return (kq >> 3) * 8 + ((kq >> 2) & 1);
}

// ---------------- tf32 GEMM: g_pre1[6400,2048] = g_embs[6400,512] @ Wih1[:, :512]^T --
__global__ __launch_bounds__(256) void pre_gemm(const float* __restrict__ B)
{
    __shared__ float As[128][36];
    __shared__ float Bs[128][36];
    const int tid = threadIdx.x;
    const int lane = tid & 31;
    const int warp = tid >> 5;
    const int wm = warp & 1;
    const int wn = warp >> 1;
    const int mBase = blockIdx.y * 128;
    const int nBase = blockIdx.x * 128;

    float acc[4][4][4];
#pragma unroll
    for (int i = 0; i < 4; i++)
#pragma unroll
        for (int j = 0; j < 4; j++)
#pragma unroll
            for (int q = 0; q < 4; q++) acc[i][j][q] = 0.f;

    const int lr = tid >> 3;
    const int kq = (tid & 7) * 4;
    const int sb = ilv_base(kq);

    for (int k0 = 0; k0 < 512; k0 += 32) {
#pragma unroll
        for (int p = 0; p < 4; p++) {
            int row = lr + p * 32;
            float4 va = *(const float4*)(g_embs + (size_t)(mBase + row) * 512 + k0 + kq);
            float4 vb = *(const float4*)(B + (size_t)(nBase + row) * 640 + k0 + kq);
            va.x = tf32r(va.x); va.y = tf32r(va.y); va.z = tf32r(va.z); va.w = tf32r(va.w);
            vb.x = tf32r(vb.x); vb.y = tf32r(vb.y); vb.z = tf32r(vb.z); vb.w = tf32r(vb.w);
            As[row][sb + 0] = va.x; As[row][sb + 2] = va.y;
            As[row][sb + 4] = va.z; As[row][sb + 6] = va.w;
            Bs[row][sb + 0] = vb.x; Bs[row][sb + 2] = vb.y;
            Bs[row][sb + 4] = vb.z; Bs[row][sb + 6] = vb.w;
        }
        __syncthreads();
#pragma unroll
        for (int ks = 0; ks < 4; ks++) {
            unsigned af[4][4], bf[4][2];
            const int ar = wm * 64 + (lane >> 2);
            const int sc = ks * 8 + 2 * (lane & 3);
#pragma unroll
            for (int mt = 0; mt < 4; mt++) {
                float2 lo = *(const float2*)&As[ar + mt * 16][sc];
                float2 hi = *(const float2*)&As[ar + mt * 16 + 8][sc];
                af[mt][0] = __float_as_uint(lo.x);
                af[mt][1] = __float_as_uint(hi.x);
                af[mt][2] = __float_as_uint(lo.y);
                af[mt][3] = __float_as_uint(hi.y);
            }
            const int br = wn * 32 + (lane >> 2);
#pragma unroll
            for (int nt = 0; nt < 4; nt++) {
                float2 vb = *(const float2*)&Bs[br + nt * 8][sc];
                bf[nt][0] = __float_as_uint(vb.x);
                bf[nt][1] = __float_as_uint(vb.y);
            }
#pragma unroll
            for (int mt = 0; mt < 4; mt++)
#pragma unroll
                for (int nt = 0; nt < 4; nt++)
                    asm volatile(
                        "mma.sync.aligned.m16n8k8.row.col.f32.tf32.tf32.f32 "
                        "{%0,%1,%2,%3},{%4,%5,%6,%7},{%8,%9},{%0,%1,%2,%3};\n"
                        : "+f"(acc[mt][nt][0]), "+f"(acc[mt][nt][1]),
                          "+f"(acc[mt][nt][2]), "+f"(acc[mt][nt][3])
                        : "r"(af[mt][0]), "r"(af[mt][1]), "r"(af[mt][2]), "r"(af[mt][3]),
                          "r"(bf[nt][0]), "r"(bf[nt][1]));
        }
        __syncthreads();
    }

#pragma unroll
    for (int mt = 0; mt < 4; mt++)
#pragma unroll
        for (int half = 0; half < 2; half++) {
            int gRow = mBase + wm * 64 + mt * 16 + (lane >> 2) + half * 8;
            float* op = g_pre1 + (size_t)gRow * G1 + nBase + wn * 32 + (lane & 3) * 2;
#pragma unroll
            for (int nt = 0; nt < 4; nt++) {
                float2 v;
                v.x = acc[mt][nt][half * 2 + 0];
                v.y = acc[mt][nt][half * 2 + 1];
                *reinterpret_cast<float2*>(op + nt * 8) = v;
            }
        }
}

// ---------------- persistent decode kernel ----------------
// smem layout (floats)
#define OFF_WS1  0
#define WS_STR   644
#define OFF_WS2  (16 * WS_STR)                 // 10304
#define OFF_US   (2 * 16 * WS_STR)             // 20608
#define OFF_GS   (OFF_US + 8192)               // 28800
#define OFF_GS2  (OFF_GS + 64 * 17)            // 29888
#define OFF_ES   (OFF_GS2 + 16 * 17)           // 30160
#define OFF_H2S  (OFF_ES + 512)                // 30672
#define OFF_RED  (OFF_H2S + 128)               // 30800
#define OFF_CTXS (OFF_RED + 64)                // 30864
#define SMEM_FLOATS (OFF_CTXS + 256)           // 31120
#define SMEM_BYTES  (SMEM_FLOATS * 4)

__global__ __launch_bounds__(256, 1) void decode_kernel(
    const float* __restrict__ enc_key, const float* __restrict__ values,
    const int* __restrict__ lens,
    const float* __restrict__ Wih1, const float* __restrict__ Whh1,
    const float* __restrict__ Wih2, const float* __restrict__ Whh2,
    float* __restrict__ attn_out)
{
    extern __shared__ float sm[];
    const int bi = blockIdx.x;
    const int tid = threadIdx.x;
    const int lane = tid & 31;
    const int wrp = tid >> 5;

    // ---- phase-A role constants: block owns d in [d0, d0+4) of h1 ----
    const int d0 = bi * 4;
    const int cidx = tid & 15;          // col within 16-col slice: gate*4+dl
    const int ngrp = tid >> 4;          // 16 batch groups of 4
    const int gateA = cidx >> 2, dlA = cidx & 3;
    const int gcol = gateA * HD + d0 + dlA;

    // ---- phase-B role constants: block owns 4 d2 x 16 batches ----
    const int d2base = (bi >> 2) * 4;
    const int nq = bi & 3;
    const int gateB = cidx >> 2, dlB = cidx & 3;
    const int g2col = gateB * KSZ + d2base + dlB;
    const int nB0 = nq * 16;

    // load weight slices into smem (once)
    for (int i = tid; i < 16 * KREC; i += 256) {
        int c = i / KREC, k = i % KREC;
        int g = (c >> 2) * HD + d0 + (c & 3);
        float w = (k < VSZ) ? Wih1[(size_t)g * (HD + VSZ) + HD + k]
                            : Whh1[(size_t)g * HD + (k - VSZ)];
        sm[OFF_WS1 + c * WS_STR + k] = w;
    }
    for (int i = tid; i < 16 * KREC; i += 256) {
        int c = i / KREC, k = i % KREC;
        int g = (c >> 2) * KSZ + d2base + (c & 3);
        float w = (k < HD) ? Wih2[(size_t)g * HD + k]
                           : Whh2[(size_t)g * KSZ + (k - HD)];
        sm[OFF_WS2 + c * WS_STR + k] = w;
    }
    __syncthreads();

    const float bias1 = g_b1[gcol];
    const float bias2 = g_b2[g2col];
    const int len = (bi < NB) ? lens[bi] : 0;
    const int kk_fix = tid & 63;
    float* US = sm + OFF_US;

    for (int t = 0; t < TD; t++) {
        // =============== PHASE A: gates1 + cell1 ===============
        {
            const float* h1r = g_h1[t & 1];
            float* h1w = g_h1[(t + 1) & 1];
            unsigned long long a0p = 0, a0q = 0, a1p = 0, a1q = 0;
            unsigned long long a2p = 0, a2q = 0, a3p = 0, a3q = 0;
            float pf[16];

            // prefetch tile 0
            {
                int k = kk_fix;
#pragma unroll
                for (int j = 0; j < 16; j++) {
                    int e = tid + j * 256, n = e >> 6;
                    pf[j] = (k < VSZ) ? g_ctx[n * VSZ + k] : h1r[n * HD + (k - VSZ)];
                }
#pragma unroll
                for (int j = 0; j < 16; j++) US[tid + j * 256] = pf[j];
            }
            __syncthreads();
            int buf = 0;
            for (int tile = 0; tile < 10; tile++) {
                if (tile < 9) {
                    int k = (tile + 1) * 64 + kk_fix;
#pragma unroll
                    for (int j = 0; j < 16; j++) {
                        int e = tid + j * 256, n = e >> 6;
                        pf[j] = (k < VSZ) ? g_ctx[n * VSZ + k] : h1r[n * HD + (k - VSZ)];
                    }
                }
                const float* W = sm + OFF_WS1 + cidx * WS_STR + tile * 64;
                const float* U = US + buf * 4096 + ngrp * 256;
#pragma unroll
                for (int kk = 0; kk < 64; kk += 4) {
                    ulonglong2 w  = *(const ulonglong2*)(W + kk);
                    ulonglong2 x0 = *(const ulonglong2*)(U + kk);
                    ulonglong2 x1 = *(const ulonglong2*)(U + 64 + kk);
                    ulonglong2 x2 = *(const ulonglong2*)(U + 128 + kk);
                    ulonglong2 x3 = *(const ulonglong2*)(U + 192 + kk);
                    FMA2(a0p, x0.x, w.x); FMA2(a0q, x0.y, w.y);
                    FMA2(a1p, x1.x, w.x); FMA2(a1q, x1.y, w.y);
                    FMA2(a2p, x2.x, w.x); FMA2(a2q, x2.y, w.y);
                    FMA2(a3p, x3.x, w.x); FMA2(a3q, x3.y, w.y);
                }
                if (tile < 9) {
                    float* D = US + (buf ^ 1) * 4096;
#pragma unroll
                    for (int j = 0; j < 16; j++) D[tid + j * 256] = pf[j];
                    __syncthreads();
                    buf ^= 1;
                }
            }
            float a0 = (f2lo(a0p) + f2hi(a0p)) + (f2lo(a0q) + f2hi(a0q));
            float a1 = (f2lo(a1p) + f2hi(a1p)) + (f2lo(a1q) + f2hi(a1q));
            float a2 = (f2lo(a2p) + f2hi(a2p)) + (f2lo(a2q) + f2hi(a2q));
            float a3 = (f2lo(a3p) + f2hi(a3p)) + (f2lo(a3q) + f2hi(a3q));
            // assemble pre-activations, exchange, cell update
            float* GS = sm + OFF_GS;
            {
                const float* pr = g_pre1 + (size_t)(t * NB) * G1 + gcol;
                int n0 = ngrp * 4;
                GS[(n0 + 0) * 17 + cidx] = a0 + __ldg(pr + (size_t)(n0 + 0) * G1) + bias1;
                GS[(n0 + 1) * 17 + cidx] = a1 + __ldg(pr + (size_t)(n0 + 1) * G1) + bias1;
                GS[(n0 + 2) * 17 + cidx] = a2 + __ldg(pr + (size_t)(n0 + 2) * G1) + bias1;
                GS[(n0 + 3) * 17 + cidx] = a3 + __ldg(pr + (size_t)(n0 + 3) * G1) + bias1;
            }
            __syncthreads();
            {
                int n = tid >> 2, dl = tid & 3;
                float gi = GS[n * 17 + 0 + dl];
                float gf = GS[n * 17 + 4 + dl];
                float gg = GS[n * 17 + 8 + dl];
                float go = GS[n * 17 + 12 + dl];
                int idx = n * HD + d0 + dl;
                float c = sigf(gf) * g_c1[idx] + sigf(gi) * tanhf(gg);
                g_c1[idx] = c;
                h1w[idx] = sigf(go) * tanhf(c);
            }
        }
        gbar();

        // =============== PHASE B: gates2 + cell2 ===============
        {
            const float* h1w = g_h1[(t + 1) & 1];
            const float* h2r = g_h2[t & 1];
            float* h2w = g_h2[(t + 1) & 1];
            unsigned long long ap2 = 0, aq2 = 0;
            float pf[4];
            {
                int k = kk_fix;
#pragma unroll
                for (int j = 0; j < 4; j++) {
                    int e = tid + j * 256, nn = e >> 6;
                    pf[j] = (k < HD) ? h1w[(nB0 + nn) * HD + k]
                                     : h2r[(nB0 + nn) * KSZ + (k - HD)];
                }
#pragma unroll
                for (int j = 0; j < 4; j++) US[tid + j * 256] = pf[j];
            }
            __syncthreads();
            int buf = 0;
            for (int tile = 0; tile < 10; tile++) {
                if (tile < 9) {
                    int k = (tile + 1) * 64 + kk_fix;
#pragma unroll
                    for (int j = 0; j < 4; j++) {
                        int e = tid + j * 256, nn = e >> 6;
                        pf[j] = (k < HD) ? h1w[(nB0 + nn) * HD + k]
                                         : h2r[(nB0 + nn) * KSZ + (k - HD)];
                    }
                }
                const float* W = sm + OFF_WS2 + cidx * WS_STR + tile * 64;
                const float* U = US + buf * 1024 + ngrp * 64;
#pragma unroll
                for (int kk = 0; kk < 64; kk += 4) {
                    ulonglong2 w = *(const ulonglong2*)(W + kk);
                    ulonglong2 x = *(const ulonglong2*)(U + kk);
                    FMA2(ap2, x.x, w.x);
                    FMA2(aq2, x.y, w.y);
                }
                if (tile < 9) {
                    float* D = US + (buf ^ 1) * 1024;
#pragma unroll
                    for (int j = 0; j < 4; j++) D[tid + j * 256] = pf[j];
                    __syncthreads();
                    buf ^= 1;
                }
            }
            float accv = (f2lo(ap2) + f2hi(ap2)) + (f2lo(aq2) + f2hi(aq2));
            float* GS2 = sm + OFF_GS2;
            GS2[ngrp * 17 + cidx] = accv + bias2;
            __syncthreads();
            if (tid < 64) {
                int ngl = tid >> 2, dl = tid & 3;
                int n = nB0 + ngl;
                float gi = GS2[ngl * 17 + 0 + dl];
                float gf = GS2[ngl * 17 + 4 + dl];
                float gg = GS2[ngl * 17 + 8 + dl];
                float go = GS2[ngl * 17 + 12 + dl];
                int idx = n * KSZ + d2base + dl;
                float c = sigf(gf) * g_c2[idx] + sigf(gi) * tanhf(gg);
                g_c2[idx] = c;
                float h = sigf(go) * tanhf(c);
                h2w[idx] = h;
                g_A[(size_t)(t * NB + n) * 256 + d2base + dl] = h;
            }
        }
        gbar();

        // =============== PHASE C: attention (64 blocks, one n each) ===============
        if (bi < NB) {
            const int n = bi;
            const float* h2w = g_h2[(t + 1) & 1];
            float* es = sm + OFF_ES;
            float* red = sm + OFF_RED;
            if (tid < KSZ) sm[OFF_H2S + tid] = h2w[n * KSZ + tid];
            __syncthreads();

            const float* ekn = enc_key + (size_t)n * TE * KSZ;
            const float4* h2s4 = (const float4*)(sm + OFF_H2S);
#pragma unroll
            for (int pass = 0; pass < 2; pass++) {
                int s = tid + pass * 256;
                const float4* row = (const float4*)(ekn + (size_t)s * KSZ);
                float e0 = 0.f, e1 = 0.f;
#pragma unroll 8
                for (int q = 0; q < 32; q += 2) {
                    float4 kv = row[q], hv = h2s4[q];
                    e0 += kv.x * hv.x + kv.y * hv.y + kv.z * hv.z + kv.w * hv.w;
                    float4 kv2 = row[q + 1], hv2 = h2s4[q + 1];
                    e1 += kv2.x * hv2.x + kv2.y * hv2.y + kv2.z * hv2.z + kv2.w * hv2.w;
                }
                es[s] = e0 + e1;
            }
            __syncthreads();

            float m = fmaxf(es[tid], es[tid + 256]);
#pragma unroll
            for (int o = 16; o; o >>= 1) m = fmaxf(m, __shfl_xor_sync(0xffffffffu, m, o));
            if (lane == 0) red[wrp] = m;
            __syncthreads();
            if (tid == 0) {
                float mm = red[0];
                for (int i = 1; i < 8; i++) mm = fmaxf(mm, red[i]);
                red[32] = mm;
            }
            __syncthreads();
            m = red[32];
            float p0 = (tid < len) ? expf(es[tid] - m) : 0.f;
            float p1 = (tid + 256 < len) ? expf(es[tid + 256] - m) : 0.f;
            float ssum = p0 + p1;
#pragma unroll
            for (int o = 16; o; o >>= 1) ssum += __shfl_xor_sync(0xffffffffu, ssum, o);
            if (lane == 0) red[wrp] = ssum;
            __syncthreads();
            if (tid == 0) {
                float ss = 0.f;
                for (int i = 0; i < 8; i++) ss += red[i];
                red[33] = ss;
            }
            __syncthreads();
            const float inv = 1.f / red[33];
            const float a0v = p0 * inv, a1v = p1 * inv;
            float* ao = attn_out + ((size_t)n * TD + t) * TE;
            ao[tid] = a0v;
            ao[tid + 256] = a1v;
            es[tid] = a0v;
            es[tid + 256] = a1v;
            __syncthreads();

            {
                int k = tid & 127, sh = tid >> 7;
                const float* vv = values + ((size_t)n * TE + sh * 256) * VSZ + k;
                const float* ap = es + sh * 256;
                float ac0 = 0.f, ac1 = 0.f, ac2 = 0.f, ac3 = 0.f;
#pragma unroll 8
                for (int s = 0; s < 256; s += 4) {
                    ac0 = fmaf(ap[s + 0], __ldg(vv + (size_t)(s + 0) * VSZ), ac0);
                    ac1 = fmaf(ap[s + 1], __ldg(vv + (size_t)(s + 1) * VSZ), ac1);
                    ac2 = fmaf(ap[s + 2], __ldg(vv + (size_t)(s + 2) * VSZ), ac2);
                    ac3 = fmaf(ap[s + 3], __ldg(vv + (size_t)(s + 3) * VSZ), ac3);
                }
                sm[OFF_CTXS + sh * 128 + k] = (ac0 + ac1) + (ac2 + ac3);
            }
            __syncthreads();
            if (tid < VSZ) {
                float cv = sm[OFF_CTXS + tid] + sm[OFF_CTXS + 128 + tid];
                g_ctx[n * VSZ + tid] = cv;
                g_A[(size_t)(t * NB + n) * 256 + KSZ + tid] = cv;
            }
        }
        gbar();
    }
}

// ---------------- final logits GEMM: out = A[6336,256] @ Wout^T + bout (tf32) -----
__global__ __launch_bounds__(256) void out_gemm(const float* __restrict__ B,
                                                const float* __restrict__ bout,
                                                float* __restrict__ out)
{
    __shared__ float As[128][36];
    __shared__ float Bs[128][36];
    const int tid = threadIdx.x;
    const int lane = tid & 31;
    const int warp = tid >> 5;
    const int wm = warp & 1;
    const int wn = warp >> 1;
    const int mBase = blockIdx.y * 128;
    const int nBase = blockIdx.x * 128;

    float acc[4][4][4];
#pragma unroll
    for (int i = 0; i < 4; i++)
#pragma unroll
        for (int j = 0; j < 4; j++)
#pragma unroll
            for (int q = 0; q < 4; q++) acc[i][j][q] = 0.f;

    const int lr = tid >> 3;
    const int kq = (tid & 7) * 4;
    const int sb = ilv_base(kq);

    for (int k0 = 0; k0 < 256; k0 += 32) {
#pragma unroll
        for (int p = 0; p < 4; p++) {
            int row = lr + p * 32;
            float4 va = *(const float4*)(g_A + (size_t)(mBase + row) * 256 + k0 + kq);
            float4 vb = *(const float4*)(B + (size_t)(nBase + row) * 256 + k0 + kq);
            va.x = tf32r(va.x); va.y = tf32r(va.y); va.z = tf32r(va.z); va.w = tf32r(va.w);
            vb.x = tf32r(vb.x); vb.y = tf32r(vb.y); vb.z = tf32r(vb.z); vb.w = tf32r(vb.w);
            As[row][sb + 0] = va.x; As[row][sb + 2] = va.y;
            As[row][sb + 4] = va.z; As[row][sb + 6] = va.w;
            Bs[row][sb + 0] = vb.x; Bs[row][sb + 2] = vb.y;
            Bs[row][sb + 4] = vb.z; Bs[row][sb + 6] = vb.w;
        }
        __syncthreads();
#pragma unroll
        for (int ks = 0; ks < 4; ks++) {
            unsigned af[4][4], bf[4][2];
            const int ar = wm * 64 + (lane >> 2);
            const int sc = ks * 8 + 2 * (lane & 3);
#pragma unroll
            for (int mt = 0; mt < 4; mt++) {
                float2 lo = *(const float2*)&As[ar + mt * 16][sc];
                float2 hi = *(const float2*)&As[ar + mt * 16 + 8][sc];
                af[mt][0] = __float_as_uint(lo.x);
                af[mt][1] = __float_as_uint(hi.x);
                af[mt][2] = __float_as_uint(lo.y);
                af[mt][3] = __float_as_uint(hi.y);
            }
            const int br = wn * 32 + (lane >> 2);
#pragma unroll
            for (int nt = 0; nt < 4; nt++) {
                float2 vb = *(const float2*)&Bs[br + nt * 8][sc];
                bf[nt][0] = __float_as_uint(vb.x);
                bf[nt][1] = __float_as_uint(vb.y);
            }
#pragma unroll
            for (int mt = 0; mt < 4; mt++)
#pragma unroll
                for (int nt = 0; nt < 4; nt++)
                    asm volatile(
                        "mma.sync.aligned.m16n8k8.row.col.f32.tf32.tf32.f32 "
                        "{%0,%1,%2,%3},{%4,%5,%6,%7},{%8,%9},{%0,%1,%2,%3};\n"
                        : "+f"(acc[mt][nt][0]), "+f"(acc[mt][nt][1]),
                          "+f"(acc[mt][nt][2]), "+f"(acc[mt][nt][3])
                        : "r"(af[mt][0]), "r"(af[mt][1]), "r"(af[mt][2]), "r"(af[mt][3]),
                          "r"(bf[nt][0]), "r"(bf[nt][1]));
        }
        __syncthreads();
    }

#pragma unroll
    for (int mt = 0; mt < 4; mt++) {
#pragma unroll
        for (int half = 0; half < 2; half++) {
            int gRow = mBase + wm * 64 + mt * 16 + (lane >> 2) + half * 8;
            if (gRow < MROWS) {
                int outRow = (gRow & 63) * TD + (gRow >> 6);
                float* op = out + (size_t)outRow * VOC + nBase + wn * 32 + (lane & 3) * 2;
#pragma unroll
                for (int nt = 0; nt < 4; nt++) {
                    int bc = nBase + wn * 32 + nt * 8 + (lane & 3) * 2;
                    float2 v;
                    v.x = acc[mt][nt][half * 2 + 0] + bout[bc];
                    v.y = acc[mt][nt][half * 2 + 1] + bout[bc + 1];
                    __stcs(reinterpret_cast<float2*>(op + nt * 8), v);
                }
            }
        }
    }
}

// ---------------- launch ----------------
extern "C" void kernel_launch(void* const* d_in, const int* in_sizes, int n_in,
                              void* d_out, int out_size)
{
    const float* enc_key   = (const float*)d_in[0];
    const float* values    = (const float*)d_in[1];
    const int*   lens      = (const int*)d_in[2];
    const int*   text      = (const int*)d_in[3];
    const float* embedding = (const float*)d_in[4];
    const float* Wih1 = (const float*)d_in[5];
    const float* Whh1 = (const float*)d_in[6];
    const float* bih1 = (const float*)d_in[7];
    const float* bhh1 = (const float*)d_in[8];
    const float* Wih2 = (const float*)d_in[9];
    const float* Whh2 = (const float*)d_in[10];
    const float* bih2 = (const float*)d_in[11];
    const float* bhh2 = (const float*)d_in[12];
    const float* Wout = (const float*)d_in[13];
    const float* bout = (const float*)d_in[14];

    float* out = (float*)d_out;
    float* attn_out = out + (size_t)MROWS * VOC;

    cudaFuncSetAttribute((const void*)decode_kernel,
                         cudaFuncAttributeMaxDynamicSharedMemorySize, SMEM_BYTES);

    setup_kernel<<<2048, 256>>>(bih1, bhh1, bih2, bhh2, embedding, text);
    pre_gemm<<<dim3(G1 / 128, MPAD / 128), 256>>>(Wih1);
    decode_kernel<<<NBLK, 256, SMEM_BYTES>>>(enc_key, values, lens,
                                             Wih1, Whh1, Wih2, Whh2, attn_out);
    out_gemm<<<dim3(VOC / 128, MPAD / 128), 256>>>(Wout, bout, out);
}